// round 1
// baseline (speedup 1.0000x reference)
#include <cuda_runtime.h>

#define B_ 2
#define T_ 1024
#define C_ 1024
#define H_ 16
#define D_ 64
#define M_ (B_*T_)   // 2048 rows for all GEMMs

// Scratch (static device globals: allocation-free per harness rules)
__device__ float g_qp[(size_t)B_*H_*T_*D_];   // [B,H,T,D]
__device__ float g_kp[(size_t)B_*H_*T_*D_];
__device__ float g_vp[(size_t)B_*H_*T_*D_];
__device__ float g_y [(size_t)M_*C_];         // attention output, [B*T, C]

// ---------------------------------------------------------------------------
// GEMM: out = X[M,K] @ W[N,K]^T + bias[N]
// 128x128 block tile, BK=16, 256 threads, 8x8 per-thread micro-tile.
// out_mode 0: row-major [M,N]; out_mode 1: scatter into [B,H,T,D] layout.
// ---------------------------------------------------------------------------
#define BM 128
#define BN 128
#define BK 16

__device__ __forceinline__ void gemm_body(
    const float* __restrict__ X, const float* __restrict__ W,
    const float* __restrict__ bias, float* __restrict__ out, int out_mode)
{
    __shared__ float As[BK][BM + 4];
    __shared__ float Bs[BK][BN + 4];

    const int tid  = threadIdx.x;          // 0..255
    const int trow = tid >> 4;              // 0..15
    const int tcol = tid & 15;              // 0..15
    const int m0 = blockIdx.y * BM;
    const int n0 = blockIdx.x * BN;
    const int K = C_, N = C_;

    float acc[8][8];
    #pragma unroll
    for (int i = 0; i < 8; i++)
        #pragma unroll
        for (int j = 0; j < 8; j++) acc[i][j] = 0.f;

    for (int k0 = 0; k0 < K; k0 += BK) {
        // cooperative load: 128 rows x 16 cols for both tiles (float4, coalesced)
        #pragma unroll
        for (int l = 0; l < 2; l++) {
            int f = tid + l * 256;          // 0..511
            int r = f >> 2;                 // 0..127
            int c = (f & 3) << 2;           // 0,4,8,12
            float4 av = *(const float4*)(X + (size_t)(m0 + r) * K + k0 + c);
            As[c][r] = av.x; As[c+1][r] = av.y; As[c+2][r] = av.z; As[c+3][r] = av.w;
            float4 bv = *(const float4*)(W + (size_t)(n0 + r) * K + k0 + c);
            Bs[c][r] = bv.x; Bs[c+1][r] = bv.y; Bs[c+2][r] = bv.z; Bs[c+3][r] = bv.w;
        }
        __syncthreads();

        #pragma unroll
        for (int kk = 0; kk < BK; kk++) {
            float a[8], b[8];
            *(float4*)&a[0] = *(const float4*)&As[kk][trow * 8];
            *(float4*)&a[4] = *(const float4*)&As[kk][trow * 8 + 4];
            *(float4*)&b[0] = *(const float4*)&Bs[kk][tcol * 8];
            *(float4*)&b[4] = *(const float4*)&Bs[kk][tcol * 8 + 4];
            #pragma unroll
            for (int i = 0; i < 8; i++)
                #pragma unroll
                for (int j = 0; j < 8; j++)
                    acc[i][j] = fmaf(a[i], b[j], acc[i][j]);
        }
        __syncthreads();
    }

    #pragma unroll
    for (int i = 0; i < 8; i++) {
        int m = m0 + trow * 8 + i;
        #pragma unroll
        for (int j = 0; j < 8; j++) {
            int n = n0 + tcol * 8 + j;
            float v = acc[i][j] + bias[n];
            if (out_mode == 0) {
                out[(size_t)m * N + n] = v;
            } else {
                int b = m >> 10, t = m & (T_ - 1);
                int h = n >> 6,  d = n & (D_ - 1);
                out[(((size_t)(b * H_ + h)) * T_ + t) * D_ + d] = v;
            }
        }
    }
}

__global__ void __launch_bounds__(256)
proj_kernel(const float* __restrict__ q, const float* __restrict__ k,
            const float* __restrict__ v, const float* __restrict__ Wk,
            const float* __restrict__ bk)
{
    const float* X = (blockIdx.z == 0) ? q : (blockIdx.z == 1) ? k : v;
    float* O = (blockIdx.z == 0) ? g_qp : (blockIdx.z == 1) ? g_kp : g_vp;
    gemm_body(X, Wk, bk, O, 1);
}

__global__ void __launch_bounds__(256)
outproj_kernel(const float* __restrict__ Wc, const float* __restrict__ bc,
               float* __restrict__ out)
{
    gemm_body(g_y, Wc, bc, out, 0);
}

// ---------------------------------------------------------------------------
// Causal flash attention, fp32. One block = one (b,h) and 64 query rows.
// 256 threads, 4x4 per-thread micro-tiles. Online softmax.
// ---------------------------------------------------------------------------
__global__ void __launch_bounds__(256)
attn_kernel()
{
    extern __shared__ float sm[];
    float* Qs = sm;                         // [64][64]
    float* Ks = Qs + 64 * 64;               // [64][65] (padded: avoids 16-way)
    float* Vs = Ks + 64 * 65;               // [64][64]
    float* Ps = Vs + 64 * 64;               // [64][64]

    const int qtile = gridDim.x - 1 - blockIdx.x;   // heavy tiles launch first
    const int bh    = blockIdx.y;                    // 0..31
    const int tid   = threadIdx.x;
    const int trow  = tid >> 4;                      // 0..15 (q rows)
    const int tcol  = tid & 15;                      // 0..15 (k cols / d cols)
    const int qr0   = trow << 2;
    const int c0    = tcol << 2;

    const float* Qg = g_qp + (size_t)bh * T_ * D_ + (size_t)qtile * 64 * D_;
    const float* Kg = g_kp + (size_t)bh * T_ * D_;
    const float* Vg = g_vp + (size_t)bh * T_ * D_;

    // load Q tile once, pre-scaled by 1/sqrt(D) = 0.125
    #pragma unroll
    for (int l = 0; l < 4; l++) {
        int f = tid + l * 256;              // 0..1023
        int r = f >> 4;
        int c = (f & 15) << 2;
        float4 v = *(const float4*)(Qg + (size_t)r * D_ + c);
        Qs[r * 64 + c]     = v.x * 0.125f;
        Qs[r * 64 + c + 1] = v.y * 0.125f;
        Qs[r * 64 + c + 2] = v.z * 0.125f;
        Qs[r * 64 + c + 3] = v.w * 0.125f;
    }

    float mrow[4] = {-1e30f, -1e30f, -1e30f, -1e30f};
    float lrow[4] = {0.f, 0.f, 0.f, 0.f};
    float O[4][4] = {};

    const int nk = qtile + 1;               // causal: only tiles <= qtile
    for (int kt = 0; kt < nk; kt++) {
        __syncthreads();                     // prev-iter Ps/Vs reads done
        #pragma unroll
        for (int l = 0; l < 4; l++) {
            int f = tid + l * 256;
            int r = f >> 4;
            int c = (f & 15) << 2;
            float4 kv = *(const float4*)(Kg + (size_t)(kt * 64 + r) * D_ + c);
            Ks[r * 65 + c]     = kv.x;
            Ks[r * 65 + c + 1] = kv.y;
            Ks[r * 65 + c + 2] = kv.z;
            Ks[r * 65 + c + 3] = kv.w;
            float4 vv = *(const float4*)(Vg + (size_t)(kt * 64 + r) * D_ + c);
            *(float4*)&Vs[r * 64 + c] = vv;
        }
        __syncthreads();

        // S = (Q/8) . K^T for this thread's 4x4 patch
        float s[4][4] = {};
        #pragma unroll 8
        for (int d = 0; d < D_; d++) {
            float qv[4], kv[4];
            #pragma unroll
            for (int i = 0; i < 4; i++) qv[i] = Qs[(qr0 + i) * 64 + d];
            #pragma unroll
            for (int j = 0; j < 4; j++) kv[j] = Ks[(c0 + j) * 65 + d];
            #pragma unroll
            for (int i = 0; i < 4; i++)
                #pragma unroll
                for (int j = 0; j < 4; j++)
                    s[i][j] = fmaf(qv[i], kv[j], s[i][j]);
        }

        // causal mask only on the diagonal tile
        if (kt == qtile) {
            #pragma unroll
            for (int i = 0; i < 4; i++)
                #pragma unroll
                for (int j = 0; j < 4; j++)
                    if (c0 + j > qr0 + i) s[i][j] = -1e30f;
        }

        // online softmax (row reductions across the 16-lane tcol group)
        #pragma unroll
        for (int i = 0; i < 4; i++) {
            float rm = fmaxf(fmaxf(s[i][0], s[i][1]), fmaxf(s[i][2], s[i][3]));
            #pragma unroll
            for (int off = 8; off; off >>= 1)
                rm = fmaxf(rm, __shfl_xor_sync(0xffffffffu, rm, off));
            float mnew = fmaxf(mrow[i], rm);
            float corr = __expf(mrow[i] - mnew);
            mrow[i] = mnew;
            float rs = 0.f;
            #pragma unroll
            for (int j = 0; j < 4; j++) {
                s[i][j] = __expf(s[i][j] - mnew);
                rs += s[i][j];
            }
            #pragma unroll
            for (int off = 8; off; off >>= 1)
                rs += __shfl_xor_sync(0xffffffffu, rs, off);
            lrow[i] = lrow[i] * corr + rs;
            #pragma unroll
            for (int j = 0; j < 4; j++) {
                O[i][j] *= corr;
                Ps[(qr0 + i) * 64 + c0 + j] = s[i][j];
            }
        }
        __syncthreads();

        // O += P . V  (thread owns d-cols c0..c0+3)
        #pragma unroll 8
        for (int k = 0; k < 64; k++) {
            float pv[4], vv[4];
            #pragma unroll
            for (int i = 0; i < 4; i++) pv[i] = Ps[(qr0 + i) * 64 + k];
            #pragma unroll
            for (int j = 0; j < 4; j++) vv[j] = Vs[k * 64 + c0 + j];
            #pragma unroll
            for (int i = 0; i < 4; i++)
                #pragma unroll
                for (int j = 0; j < 4; j++)
                    O[i][j] = fmaf(pv[i], vv[j], O[i][j]);
        }
    }

    // write y in [B*T, C] layout: y[b,t, h*64 + d]
    const int b = bh >> 4, h = bh & 15;
    #pragma unroll
    for (int i = 0; i < 4; i++) {
        int t = qtile * 64 + qr0 + i;
        float inv = 1.0f / lrow[i];
        #pragma unroll
        for (int j = 0; j < 4; j++)
            g_y[((size_t)(b * T_ + t)) * C_ + h * D_ + c0 + j] = O[i][j] * inv;
    }
}

// ---------------------------------------------------------------------------
extern "C" void kernel_launch(void* const* d_in, const int* in_sizes, int n_in,
                              void* d_out, int out_size)
{
    const float* q  = (const float*)d_in[0];
    const float* k  = (const float*)d_in[1];
    const float* v  = (const float*)d_in[2];
    // d_in[3] = causal mask (unused: causality handled analytically)
    const float* Wk = (const float*)d_in[4];
    const float* bk = (const float*)d_in[5];
    const float* Wc = (const float*)d_in[6];
    const float* bc = (const float*)d_in[7];
    float* out = (float*)d_out;

    // 1) fused Q/K/V projection into [B,H,T,D] scratch
    proj_kernel<<<dim3(C_/BN, M_/BM, 3), 256>>>(q, k, v, Wk, bk);

    // 2) causal flash attention -> g_y [B*T, C]
    const size_t attn_smem = (size_t)(64*64 + 64*65 + 64*64 + 64*64) * sizeof(float);
    cudaFuncSetAttribute(attn_kernel, cudaFuncAttributeMaxDynamicSharedMemorySize,
                         (int)attn_smem);
    attn_kernel<<<dim3(T_/64, B_*H_), 256, attn_smem>>>();

    // 3) output projection -> d_out
    outproj_kernel<<<dim3(C_/BN, M_/BM, 1), 256>>>(Wc, bc, out);
}

// round 2
// speedup vs baseline: 1.0020x; 1.0020x over previous
#include <cuda_runtime.h>

#define B_ 2
#define T_ 1024
#define C_ 1024
#define H_ 16
#define D_ 64
#define M_ (B_*T_)   // 2048 rows for all GEMMs

// Scratch (static device globals: allocation-free per harness rules)
__device__ float g_qp[(size_t)B_*H_*T_*D_];   // [B,H,T,D]
__device__ float g_kp[(size_t)B_*H_*T_*D_];
__device__ float g_vp[(size_t)B_*H_*T_*D_];
__device__ float g_y [(size_t)M_*C_];         // attention output, [B*T, C]

// ---------------------------------------------------------------------------
// GEMM: out = X[M,K] @ W[N,K]^T + bias[N]
// 128x128 block tile, BK=16, 256 threads, 8x8 per-thread micro-tile.
// out_mode 0: row-major [M,N]; out_mode 1: scatter into [B,H,T,D] layout.
// ---------------------------------------------------------------------------
#define BM 128
#define BN 128
#define BK 16

__device__ __forceinline__ void gemm_body(
    const float* __restrict__ X, const float* __restrict__ W,
    const float* __restrict__ bias, float* __restrict__ out, int out_mode)
{
    __shared__ float As[BK][BM + 4];
    __shared__ float Bs[BK][BN + 4];

    const int tid  = threadIdx.x;          // 0..255
    const int trow = tid >> 4;              // 0..15
    const int tcol = tid & 15;              // 0..15
    const int m0 = blockIdx.y * BM;
    const int n0 = blockIdx.x * BN;
    const int K = C_, N = C_;

    float acc[8][8];
    #pragma unroll
    for (int i = 0; i < 8; i++)
        #pragma unroll
        for (int j = 0; j < 8; j++) acc[i][j] = 0.f;

    for (int k0 = 0; k0 < K; k0 += BK) {
        // cooperative load: 128 rows x 16 cols for both tiles (float4, coalesced)
        #pragma unroll
        for (int l = 0; l < 2; l++) {
            int f = tid + l * 256;          // 0..511
            int r = f >> 2;                 // 0..127
            int c = (f & 3) << 2;           // 0,4,8,12
            float4 av = *(const float4*)(X + (size_t)(m0 + r) * K + k0 + c);
            As[c][r] = av.x; As[c+1][r] = av.y; As[c+2][r] = av.z; As[c+3][r] = av.w;
            float4 bv = *(const float4*)(W + (size_t)(n0 + r) * K + k0 + c);
            Bs[c][r] = bv.x; Bs[c+1][r] = bv.y; Bs[c+2][r] = bv.z; Bs[c+3][r] = bv.w;
        }
        __syncthreads();

        #pragma unroll
        for (int kk = 0; kk < BK; kk++) {
            float a[8], b[8];
            *(float4*)&a[0] = *(const float4*)&As[kk][trow * 8];
            *(float4*)&a[4] = *(const float4*)&As[kk][trow * 8 + 4];
            *(float4*)&b[0] = *(const float4*)&Bs[kk][tcol * 8];
            *(float4*)&b[4] = *(const float4*)&Bs[kk][tcol * 8 + 4];
            #pragma unroll
            for (int i = 0; i < 8; i++)
                #pragma unroll
                for (int j = 0; j < 8; j++)
                    acc[i][j] = fmaf(a[i], b[j], acc[i][j]);
        }
        __syncthreads();
    }

    #pragma unroll
    for (int i = 0; i < 8; i++) {
        int m = m0 + trow * 8 + i;
        #pragma unroll
        for (int j = 0; j < 8; j++) {
            int n = n0 + tcol * 8 + j;
            float v = acc[i][j] + bias[n];
            if (out_mode == 0) {
                out[(size_t)m * N + n] = v;
            } else {
                int b = m >> 10, t = m & (T_ - 1);
                int h = n >> 6,  d = n & (D_ - 1);
                out[(((size_t)(b * H_ + h)) * T_ + t) * D_ + d] = v;
            }
        }
    }
}

__global__ void __launch_bounds__(256)
proj_kernel(const float* __restrict__ q, const float* __restrict__ k,
            const float* __restrict__ v, const float* __restrict__ Wk,
            const float* __restrict__ bk)
{
    const float* X = (blockIdx.z == 0) ? q : (blockIdx.z == 1) ? k : v;
    float* O = (blockIdx.z == 0) ? g_qp : (blockIdx.z == 1) ? g_kp : g_vp;
    gemm_body(X, Wk, bk, O, 1);
}

__global__ void __launch_bounds__(256)
outproj_kernel(const float* __restrict__ Wc, const float* __restrict__ bc,
               float* __restrict__ out)
{
    gemm_body(g_y, Wc, bc, out, 0);
}

// ---------------------------------------------------------------------------
// Causal flash attention, fp32. One block = one (b,h) and 64 query rows.
// 256 threads, 4x4 per-thread micro-tiles. Online softmax.
// ---------------------------------------------------------------------------
__global__ void __launch_bounds__(256)
attn_kernel()
{
    extern __shared__ float sm[];
    float* Qs = sm;                         // [64][64]
    float* Ks = Qs + 64 * 64;               // [64][65] (padded: avoids 16-way)
    float* Vs = Ks + 64 * 65;               // [64][64]
    float* Ps = Vs + 64 * 64;               // [64][64]

    const int qtile = gridDim.x - 1 - blockIdx.x;   // heavy tiles launch first
    const int bh    = blockIdx.y;                    // 0..31
    const int tid   = threadIdx.x;
    const int trow  = tid >> 4;                      // 0..15 (q rows)
    const int tcol  = tid & 15;                      // 0..15 (k cols / d cols)
    const int qr0   = trow << 2;
    const int c0    = tcol << 2;

    const float* Qg = g_qp + (size_t)bh * T_ * D_ + (size_t)qtile * 64 * D_;
    const float* Kg = g_kp + (size_t)bh * T_ * D_;
    const float* Vg = g_vp + (size_t)bh * T_ * D_;

    // load Q tile once, pre-scaled by 1/sqrt(D) = 0.125
    #pragma unroll
    for (int l = 0; l < 4; l++) {
        int f = tid + l * 256;              // 0..1023
        int r = f >> 4;
        int c = (f & 15) << 2;
        float4 v = *(const float4*)(Qg + (size_t)r * D_ + c);
        Qs[r * 64 + c]     = v.x * 0.125f;
        Qs[r * 64 + c + 1] = v.y * 0.125f;
        Qs[r * 64 + c + 2] = v.z * 0.125f;
        Qs[r * 64 + c + 3] = v.w * 0.125f;
    }

    float mrow[4] = {-1e30f, -1e30f, -1e30f, -1e30f};
    float lrow[4] = {0.f, 0.f, 0.f, 0.f};
    float O[4][4] = {};

    const int nk = qtile + 1;               // causal: only tiles <= qtile
    for (int kt = 0; kt < nk; kt++) {
        __syncthreads();                     // prev-iter Ps/Vs reads done
        #pragma unroll
        for (int l = 0; l < 4; l++) {
            int f = tid + l * 256;
            int r = f >> 4;
            int c = (f & 15) << 2;
            float4 kv = *(const float4*)(Kg + (size_t)(kt * 64 + r) * D_ + c);
            Ks[r * 65 + c]     = kv.x;
            Ks[r * 65 + c + 1] = kv.y;
            Ks[r * 65 + c + 2] = kv.z;
            Ks[r * 65 + c + 3] = kv.w;
            float4 vv = *(const float4*)(Vg + (size_t)(kt * 64 + r) * D_ + c);
            *(float4*)&Vs[r * 64 + c] = vv;
        }
        __syncthreads();

        // S = (Q/8) . K^T for this thread's 4x4 patch
        float s[4][4] = {};
        #pragma unroll 8
        for (int d = 0; d < D_; d++) {
            float qv[4], kv[4];
            #pragma unroll
            for (int i = 0; i < 4; i++) qv[i] = Qs[(qr0 + i) * 64 + d];
            #pragma unroll
            for (int j = 0; j < 4; j++) kv[j] = Ks[(c0 + j) * 65 + d];
            #pragma unroll
            for (int i = 0; i < 4; i++)
                #pragma unroll
                for (int j = 0; j < 4; j++)
                    s[i][j] = fmaf(qv[i], kv[j], s[i][j]);
        }

        // causal mask only on the diagonal tile
        if (kt == qtile) {
            #pragma unroll
            for (int i = 0; i < 4; i++)
                #pragma unroll
                for (int j = 0; j < 4; j++)
                    if (c0 + j > qr0 + i) s[i][j] = -1e30f;
        }

        // online softmax (row reductions across the 16-lane tcol group)
        #pragma unroll
        for (int i = 0; i < 4; i++) {
            float rm = fmaxf(fmaxf(s[i][0], s[i][1]), fmaxf(s[i][2], s[i][3]));
            #pragma unroll
            for (int off = 8; off; off >>= 1)
                rm = fmaxf(rm, __shfl_xor_sync(0xffffffffu, rm, off));
            float mnew = fmaxf(mrow[i], rm);
            float corr = __expf(mrow[i] - mnew);
            mrow[i] = mnew;
            float rs = 0.f;
            #pragma unroll
            for (int j = 0; j < 4; j++) {
                s[i][j] = __expf(s[i][j] - mnew);
                rs += s[i][j];
            }
            #pragma unroll
            for (int off = 8; off; off >>= 1)
                rs += __shfl_xor_sync(0xffffffffu, rs, off);
            lrow[i] = lrow[i] * corr + rs;
            #pragma unroll
            for (int j = 0; j < 4; j++) {
                O[i][j] *= corr;
                Ps[(qr0 + i) * 64 + c0 + j] = s[i][j];
            }
        }
        __syncthreads();

        // O += P . V  (thread owns d-cols c0..c0+3)
        #pragma unroll 8
        for (int k = 0; k < 64; k++) {
            float pv[4], vv[4];
            #pragma unroll
            for (int i = 0; i < 4; i++) pv[i] = Ps[(qr0 + i) * 64 + k];
            #pragma unroll
            for (int j = 0; j < 4; j++) vv[j] = Vs[k * 64 + c0 + j];
            #pragma unroll
            for (int i = 0; i < 4; i++)
                #pragma unroll
                for (int j = 0; j < 4; j++)
                    O[i][j] = fmaf(pv[i], vv[j], O[i][j]);
        }
    }

    // write y in [B*T, C] layout: y[b,t, h*64 + d]
    const int b = bh >> 4, h = bh & 15;
    #pragma unroll
    for (int i = 0; i < 4; i++) {
        int t = qtile * 64 + qr0 + i;
        float inv = 1.0f / lrow[i];
        #pragma unroll
        for (int j = 0; j < 4; j++)
            g_y[((size_t)(b * T_ + t)) * C_ + h * D_ + c0 + j] = O[i][j] * inv;
    }
}

// ---------------------------------------------------------------------------
extern "C" void kernel_launch(void* const* d_in, const int* in_sizes, int n_in,
                              void* d_out, int out_size)
{
    const float* q  = (const float*)d_in[0];
    const float* k  = (const float*)d_in[1];
    const float* v  = (const float*)d_in[2];
    // d_in[3] = causal mask (unused: causality handled analytically)
    const float* Wk = (const float*)d_in[4];
    const float* bk = (const float*)d_in[5];
    const float* Wc = (const float*)d_in[6];
    const float* bc = (const float*)d_in[7];
    float* out = (float*)d_out;

    // 1) fused Q/K/V projection into [B,H,T,D] scratch
    proj_kernel<<<dim3(C_/BN, M_/BM, 3), 256>>>(q, k, v, Wk, bk);

    // 2) causal flash attention -> g_y [B*T, C]
    const size_t attn_smem = (size_t)(64*64 + 64*65 + 64*64 + 64*64) * sizeof(float);
    cudaFuncSetAttribute(attn_kernel, cudaFuncAttributeMaxDynamicSharedMemorySize,
                         (int)attn_smem);
    attn_kernel<<<dim3(T_/64, B_*H_), 256, attn_smem>>>();

    // 3) output projection -> d_out
    outproj_kernel<<<dim3(C_/BN, M_/BM, 1), 256>>>(Wc, bc, out);
}

// round 4
// speedup vs baseline: 2.1565x; 2.1522x over previous
#include <cuda_runtime.h>
#include <cstdint>

#define B_ 2
#define T_ 1024
#define C_ 1024
#define H_ 16
#define D_ 64
#define M_ (B_*T_)   // 2048 rows

// Scratch (static device globals: allocation-free per harness rules)
__device__ float g_qp[(size_t)B_*H_*T_*D_];   // [B,H,T,D]
__device__ float g_kp[(size_t)B_*H_*T_*D_];
__device__ float g_vp[(size_t)B_*H_*T_*D_];
__device__ float g_y [(size_t)M_*C_];         // attention output, [B*T, C]

__device__ __forceinline__ uint32_t smem_u32(const void* p) {
    uint32_t a;
    asm("{ .reg .u64 t; cvta.to.shared.u64 t, %1; cvt.u32.u64 %0, t; }"
        : "=r"(a) : "l"(p));
    return a;
}

__device__ __forceinline__ uint32_t f2tf32(float x) {
    uint32_t t;
    asm("cvt.rna.tf32.f32 %0, %1;" : "=r"(t) : "f"(x));
    return t;
}

// ---------------------------------------------------------------------------
// tf32 mma.sync GEMM: out = X[M,1024] @ W[1024,1024]^T + bias[1024]
// CTA 128x128, BK=32, 256 threads (8 warps as 2x4), warp tile 64x32.
// Double-buffered cp.async. out_mode 0: [M,N] row-major; 1: [B,H,T,D] scatter.
// ---------------------------------------------------------------------------
#define BM 128
#define BN 128
#define BK 32
#define LDS_ 36                          // row stride in floats (pad 4)
#define BUF_FLOATS (BM * LDS_)           // 4608 floats per A/B buffer
#define SMEM_GEMM_BYTES (4 * BUF_FLOATS * 4)   // 73728

__device__ __forceinline__ void mma_tf32(
    float* c, uint32_t a0, uint32_t a1, uint32_t a2, uint32_t a3,
    uint32_t b0, uint32_t b1)
{
    asm volatile(
        "mma.sync.aligned.m16n8k8.row.col.f32.tf32.tf32.f32 "
        "{%0,%1,%2,%3}, {%4,%5,%6,%7}, {%8,%9}, {%0,%1,%2,%3};"
        : "+f"(c[0]), "+f"(c[1]), "+f"(c[2]), "+f"(c[3])
        : "r"(a0), "r"(a1), "r"(a2), "r"(a3), "r"(b0), "r"(b1));
}

__device__ __forceinline__ void gemm_tc(
    const float* __restrict__ X, const float* __restrict__ W,
    const float* __restrict__ bias, float* __restrict__ out, int out_mode)
{
    extern __shared__ float sm[];
    float* As[2] = { sm,                  sm + BUF_FLOATS };
    float* Bs[2] = { sm + 2*BUF_FLOATS,   sm + 3*BUF_FLOATS };

    const int tid  = threadIdx.x;
    const int wid  = tid >> 5;
    const int lane = tid & 31;
    const int wr   = wid >> 2;            // 0..1
    const int wc   = wid & 3;             // 0..3
    const int warpM = wr * 64;
    const int warpN = wc * 32;
    const int m0 = blockIdx.y * BM;
    const int n0 = blockIdx.x * BN;
    const int lr = lane >> 2;             // 0..7
    const int lc = lane & 3;              // 0..3

    float acc[4][4][4];
    #pragma unroll
    for (int i = 0; i < 4; i++)
        #pragma unroll
        for (int j = 0; j < 4; j++)
            #pragma unroll
            for (int e = 0; e < 4; e++) acc[i][j][e] = 0.f;

    // async load of one 128x32 chunk into buffer s (A from X, B from W)
    auto load_chunk = [&](int ch, int s) {
        const uint32_t aBase = smem_u32(As[s]);
        const uint32_t bBase = smem_u32(Bs[s]);
        #pragma unroll
        for (int i = 0; i < 4; i++) {
            int idx = tid + i * 256;      // 0..1023
            int r   = idx >> 3;           // 0..127
            int c4  = idx & 7;            // 0..7  (float4 column)
            uint32_t soff = (uint32_t)(r * LDS_ + c4 * 4) * 4;
            const float* gA = X + (size_t)(m0 + r) * C_ + ch * BK + c4 * 4;
            asm volatile("cp.async.cg.shared.global [%0], [%1], 16;"
                         :: "r"(aBase + soff), "l"(gA));
            const float* gB = W + (size_t)(n0 + r) * C_ + ch * BK + c4 * 4;
            asm volatile("cp.async.cg.shared.global [%0], [%1], 16;"
                         :: "r"(bBase + soff), "l"(gB));
        }
        asm volatile("cp.async.commit_group;" ::: "memory");
    };

    const int NCH = C_ / BK;              // 32
    load_chunk(0, 0);

    for (int ch = 0; ch < NCH; ch++) {
        const int s = ch & 1;
        if (ch + 1 < NCH) load_chunk(ch + 1, s ^ 1);
        if (ch + 1 < NCH)
            asm volatile("cp.async.wait_group 1;" ::: "memory");
        else
            asm volatile("cp.async.wait_group 0;" ::: "memory");
        __syncthreads();

        const float* A = As[s];
        const float* Bm = Bs[s];
        #pragma unroll
        for (int kk = 0; kk < BK; kk += 8) {
            // B fragments: Bs[n][k], b0 k=kk+lc, b1 k=kk+lc+4, n = warpN+ni*8+lr
            uint32_t bf[4][2];
            #pragma unroll
            for (int ni = 0; ni < 4; ni++) {
                const float* bp = Bm + (warpN + ni * 8 + lr) * LDS_ + kk + lc;
                bf[ni][0] = f2tf32(bp[0]);
                bf[ni][1] = f2tf32(bp[4]);
            }
            #pragma unroll
            for (int mi = 0; mi < 4; mi++) {
                const float* ap = A + (warpM + mi * 16 + lr) * LDS_ + kk + lc;
                uint32_t a0 = f2tf32(ap[0]);
                uint32_t a1 = f2tf32(ap[8 * LDS_]);
                uint32_t a2 = f2tf32(ap[4]);
                uint32_t a3 = f2tf32(ap[8 * LDS_ + 4]);
                #pragma unroll
                for (int ni = 0; ni < 4; ni++)
                    mma_tf32(acc[mi][ni], a0, a1, a2, a3, bf[ni][0], bf[ni][1]);
            }
        }
        __syncthreads();
    }

    // epilogue: c0,c1 -> (row, col..col+1); c2,c3 -> (row+8, col..col+1)
    #pragma unroll
    for (int mi = 0; mi < 4; mi++) {
        #pragma unroll
        for (int rr = 0; rr < 2; rr++) {
            const int m = m0 + warpM + mi * 16 + lr + rr * 8;
            #pragma unroll
            for (int ni = 0; ni < 4; ni++) {
                const int n = n0 + warpN + ni * 8 + lc * 2;
                float2 vv;
                vv.x = acc[mi][ni][rr * 2 + 0] + bias[n];
                vv.y = acc[mi][ni][rr * 2 + 1] + bias[n + 1];
                if (out_mode == 0) {
                    *(float2*)(out + (size_t)m * C_ + n) = vv;
                } else {
                    const int b = m >> 10, t = m & (T_ - 1);
                    const int h = n >> 6,  d0 = n & (D_ - 1);
                    *(float2*)(out + (((size_t)(b * H_ + h)) * T_ + t) * D_ + d0) = vv;
                }
            }
        }
    }
}

__global__ void __launch_bounds__(256)
proj_tc_kernel(const float* __restrict__ q, const float* __restrict__ k,
               const float* __restrict__ v, const float* __restrict__ Wk,
               const float* __restrict__ bk)
{
    const float* X = (blockIdx.z == 0) ? q : (blockIdx.z == 1) ? k : v;
    float* O = (blockIdx.z == 0) ? g_qp : (blockIdx.z == 1) ? g_kp : g_vp;
    gemm_tc(X, Wk, bk, O, 1);
}

__global__ void __launch_bounds__(256)
outproj_tc_kernel(const float* __restrict__ Wc, const float* __restrict__ bc,
                  float* __restrict__ out)
{
    gemm_tc(g_y, Wc, bc, out, 0);
}

// ---------------------------------------------------------------------------
// Causal flash attention, fp32 (unchanged from passing R1 version).
// ---------------------------------------------------------------------------
__global__ void __launch_bounds__(256)
attn_kernel()
{
    extern __shared__ float smf[];
    float* Qs = smf;                        // [64][64]
    float* Ks = Qs + 64 * 64;               // [64][65]
    float* Vs = Ks + 64 * 65;               // [64][64]
    float* Ps = Vs + 64 * 64;               // [64][64]

    const int qtile = gridDim.x - 1 - blockIdx.x;
    const int bh    = blockIdx.y;
    const int tid   = threadIdx.x;
    const int trow  = tid >> 4;
    const int tcol  = tid & 15;
    const int qr0   = trow << 2;
    const int c0    = tcol << 2;

    const float* Qg = g_qp + (size_t)bh * T_ * D_ + (size_t)qtile * 64 * D_;
    const float* Kg = g_kp + (size_t)bh * T_ * D_;
    const float* Vg = g_vp + (size_t)bh * T_ * D_;

    #pragma unroll
    for (int l = 0; l < 4; l++) {
        int f = tid + l * 256;
        int r = f >> 4;
        int c = (f & 15) << 2;
        float4 v = *(const float4*)(Qg + (size_t)r * D_ + c);
        Qs[r * 64 + c]     = v.x * 0.125f;
        Qs[r * 64 + c + 1] = v.y * 0.125f;
        Qs[r * 64 + c + 2] = v.z * 0.125f;
        Qs[r * 64 + c + 3] = v.w * 0.125f;
    }

    float mrow[4] = {-1e30f, -1e30f, -1e30f, -1e30f};
    float lrow[4] = {0.f, 0.f, 0.f, 0.f};
    float O[4][4] = {};

    const int nk = qtile + 1;
    for (int kt = 0; kt < nk; kt++) {
        __syncthreads();
        #pragma unroll
        for (int l = 0; l < 4; l++) {
            int f = tid + l * 256;
            int r = f >> 4;
            int c = (f & 15) << 2;
            float4 kv = *(const float4*)(Kg + (size_t)(kt * 64 + r) * D_ + c);
            Ks[r * 65 + c]     = kv.x;
            Ks[r * 65 + c + 1] = kv.y;
            Ks[r * 65 + c + 2] = kv.z;
            Ks[r * 65 + c + 3] = kv.w;
            float4 vv = *(const float4*)(Vg + (size_t)(kt * 64 + r) * D_ + c);
            *(float4*)&Vs[r * 64 + c] = vv;
        }
        __syncthreads();

        float s[4][4] = {};
        #pragma unroll 8
        for (int d = 0; d < D_; d++) {
            float qv[4], kv[4];
            #pragma unroll
            for (int i = 0; i < 4; i++) qv[i] = Qs[(qr0 + i) * 64 + d];
            #pragma unroll
            for (int j = 0; j < 4; j++) kv[j] = Ks[(c0 + j) * 65 + d];
            #pragma unroll
            for (int i = 0; i < 4; i++)
                #pragma unroll
                for (int j = 0; j < 4; j++)
                    s[i][j] = fmaf(qv[i], kv[j], s[i][j]);
        }

        if (kt == qtile) {
            #pragma unroll
            for (int i = 0; i < 4; i++)
                #pragma unroll
                for (int j = 0; j < 4; j++)
                    if (c0 + j > qr0 + i) s[i][j] = -1e30f;
        }

        #pragma unroll
        for (int i = 0; i < 4; i++) {
            float rm = fmaxf(fmaxf(s[i][0], s[i][1]), fmaxf(s[i][2], s[i][3]));
            #pragma unroll
            for (int off = 8; off; off >>= 1)
                rm = fmaxf(rm, __shfl_xor_sync(0xffffffffu, rm, off));
            float mnew = fmaxf(mrow[i], rm);
            float corr = __expf(mrow[i] - mnew);
            mrow[i] = mnew;
            float rs = 0.f;
            #pragma unroll
            for (int j = 0; j < 4; j++) {
                s[i][j] = __expf(s[i][j] - mnew);
                rs += s[i][j];
            }
            #pragma unroll
            for (int off = 8; off; off >>= 1)
                rs += __shfl_xor_sync(0xffffffffu, rs, off);
            lrow[i] = lrow[i] * corr + rs;
            #pragma unroll
            for (int j = 0; j < 4; j++) {
                O[i][j] *= corr;
                Ps[(qr0 + i) * 64 + c0 + j] = s[i][j];
            }
        }
        __syncthreads();

        #pragma unroll 8
        for (int k = 0; k < 64; k++) {
            float pv[4], vv[4];
            #pragma unroll
            for (int i = 0; i < 4; i++) pv[i] = Ps[(qr0 + i) * 64 + k];
            #pragma unroll
            for (int j = 0; j < 4; j++) vv[j] = Vs[k * 64 + c0 + j];
            #pragma unroll
            for (int i = 0; i < 4; i++)
                #pragma unroll
                for (int j = 0; j < 4; j++)
                    O[i][j] = fmaf(pv[i], vv[j], O[i][j]);
        }
    }

    const int b = bh >> 4, h = bh & 15;
    #pragma unroll
    for (int i = 0; i < 4; i++) {
        int t = qtile * 64 + qr0 + i;
        float inv = 1.0f / lrow[i];
        #pragma unroll
        for (int j = 0; j < 4; j++)
            g_y[((size_t)(b * T_ + t)) * C_ + h * D_ + c0 + j] = O[i][j] * inv;
    }
}

// ---------------------------------------------------------------------------
extern "C" void kernel_launch(void* const* d_in, const int* in_sizes, int n_in,
                              void* d_out, int out_size)
{
    const float* q  = (const float*)d_in[0];
    const float* k  = (const float*)d_in[1];
    const float* v  = (const float*)d_in[2];
    // d_in[3] = causal mask (unused: causality handled analytically)
    const float* Wk = (const float*)d_in[4];
    const float* bk = (const float*)d_in[5];
    const float* Wc = (const float*)d_in[6];
    const float* bc = (const float*)d_in[7];
    float* out = (float*)d_out;

    const size_t attn_smem = (size_t)(64*64 + 64*65 + 64*64 + 64*64) * sizeof(float);
    cudaFuncSetAttribute(proj_tc_kernel,
                         cudaFuncAttributeMaxDynamicSharedMemorySize, SMEM_GEMM_BYTES);
    cudaFuncSetAttribute(outproj_tc_kernel,
                         cudaFuncAttributeMaxDynamicSharedMemorySize, SMEM_GEMM_BYTES);
    cudaFuncSetAttribute(attn_kernel,
                         cudaFuncAttributeMaxDynamicSharedMemorySize, (int)attn_smem);

    // 1) fused Q/K/V projection (tf32 mma.sync) -> [B,H,T,D] scratch
    proj_tc_kernel<<<dim3(C_/BN, M_/BM, 3), 256, SMEM_GEMM_BYTES>>>(q, k, v, Wk, bk);

    // 2) causal flash attention -> g_y [B*T, C]
    attn_kernel<<<dim3(T_/64, B_*H_), 256, attn_smem>>>();

    // 3) output projection (tf32 mma.sync) -> d_out
    outproj_tc_kernel<<<dim3(C_/BN, M_/BM, 1), 256, SMEM_GEMM_BYTES>>>(Wc, bc, out);
}

// round 5
// speedup vs baseline: 3.0732x; 1.4251x over previous
#include <cuda_runtime.h>
#include <cstdint>

#define B_ 2
#define T_ 1024
#define C_ 1024
#define H_ 16
#define D_ 64
#define M_ (B_*T_)   // 2048 rows

// Scratch (static device globals: allocation-free per harness rules)
__device__ float g_qp[(size_t)B_*H_*T_*D_];   // [B,H,T,D]
__device__ float g_kp[(size_t)B_*H_*T_*D_];
__device__ float g_vp[(size_t)B_*H_*T_*D_];
__device__ float g_y [(size_t)M_*C_];         // attention output, [B*T, C]

__device__ __forceinline__ uint32_t smem_u32(const void* p) {
    uint32_t a;
    asm("{ .reg .u64 t; cvta.to.shared.u64 t, %1; cvt.u32.u64 %0, t; }"
        : "=r"(a) : "l"(p));
    return a;
}

__device__ __forceinline__ uint32_t f2tf32(float x) {
    uint32_t t;
    asm("cvt.rna.tf32.f32 %0, %1;" : "=r"(t) : "f"(x));
    return t;
}

__device__ __forceinline__ void mma_tf32(
    float* c, uint32_t a0, uint32_t a1, uint32_t a2, uint32_t a3,
    uint32_t b0, uint32_t b1)
{
    asm volatile(
        "mma.sync.aligned.m16n8k8.row.col.f32.tf32.tf32.f32 "
        "{%0,%1,%2,%3}, {%4,%5,%6,%7}, {%8,%9}, {%0,%1,%2,%3};"
        : "+f"(c[0]), "+f"(c[1]), "+f"(c[2]), "+f"(c[3])
        : "r"(a0), "r"(a1), "r"(a2), "r"(a3), "r"(b0), "r"(b1));
}

// ---------------------------------------------------------------------------
// tf32 mma.sync GEMM: out = X[M,1024] @ W[1024,1024]^T + bias[1024]
// CTA 128x128, BK=32, 256 threads (8 warps as 2x4), warp tile 64x32.
// ---------------------------------------------------------------------------
#define BM 128
#define BN 128
#define BK 32
#define LDS_ 36
#define BUF_FLOATS (BM * LDS_)
#define SMEM_GEMM_BYTES (4 * BUF_FLOATS * 4)   // 73728

__device__ __forceinline__ void gemm_tc(
    const float* __restrict__ X, const float* __restrict__ W,
    const float* __restrict__ bias, float* __restrict__ out, int out_mode)
{
    extern __shared__ float sm[];
    float* As[2] = { sm,                  sm + BUF_FLOATS };
    float* Bs[2] = { sm + 2*BUF_FLOATS,   sm + 3*BUF_FLOATS };

    const int tid  = threadIdx.x;
    const int wid  = tid >> 5;
    const int lane = tid & 31;
    const int wr   = wid >> 2;
    const int wc   = wid & 3;
    const int warpM = wr * 64;
    const int warpN = wc * 32;
    const int m0 = blockIdx.y * BM;
    const int n0 = blockIdx.x * BN;
    const int lr = lane >> 2;
    const int lc = lane & 3;

    float acc[4][4][4];
    #pragma unroll
    for (int i = 0; i < 4; i++)
        #pragma unroll
        for (int j = 0; j < 4; j++)
            #pragma unroll
            for (int e = 0; e < 4; e++) acc[i][j][e] = 0.f;

    auto load_chunk = [&](int ch, int s) {
        const uint32_t aBase = smem_u32(As[s]);
        const uint32_t bBase = smem_u32(Bs[s]);
        #pragma unroll
        for (int i = 0; i < 4; i++) {
            int idx = tid + i * 256;
            int r   = idx >> 3;
            int c4  = idx & 7;
            uint32_t soff = (uint32_t)(r * LDS_ + c4 * 4) * 4;
            const float* gA = X + (size_t)(m0 + r) * C_ + ch * BK + c4 * 4;
            asm volatile("cp.async.cg.shared.global [%0], [%1], 16;"
                         :: "r"(aBase + soff), "l"(gA));
            const float* gB = W + (size_t)(n0 + r) * C_ + ch * BK + c4 * 4;
            asm volatile("cp.async.cg.shared.global [%0], [%1], 16;"
                         :: "r"(bBase + soff), "l"(gB));
        }
        asm volatile("cp.async.commit_group;" ::: "memory");
    };

    const int NCH = C_ / BK;
    load_chunk(0, 0);

    for (int ch = 0; ch < NCH; ch++) {
        const int s = ch & 1;
        if (ch + 1 < NCH) load_chunk(ch + 1, s ^ 1);
        if (ch + 1 < NCH)
            asm volatile("cp.async.wait_group 1;" ::: "memory");
        else
            asm volatile("cp.async.wait_group 0;" ::: "memory");
        __syncthreads();

        const float* A = As[s];
        const float* Bm = Bs[s];
        #pragma unroll
        for (int kk = 0; kk < BK; kk += 8) {
            uint32_t bf[4][2];
            #pragma unroll
            for (int ni = 0; ni < 4; ni++) {
                const float* bp = Bm + (warpN + ni * 8 + lr) * LDS_ + kk + lc;
                bf[ni][0] = f2tf32(bp[0]);
                bf[ni][1] = f2tf32(bp[4]);
            }
            #pragma unroll
            for (int mi = 0; mi < 4; mi++) {
                const float* ap = A + (warpM + mi * 16 + lr) * LDS_ + kk + lc;
                uint32_t a0 = f2tf32(ap[0]);
                uint32_t a1 = f2tf32(ap[8 * LDS_]);
                uint32_t a2 = f2tf32(ap[4]);
                uint32_t a3 = f2tf32(ap[8 * LDS_ + 4]);
                #pragma unroll
                for (int ni = 0; ni < 4; ni++)
                    mma_tf32(acc[mi][ni], a0, a1, a2, a3, bf[ni][0], bf[ni][1]);
            }
        }
        __syncthreads();
    }

    #pragma unroll
    for (int mi = 0; mi < 4; mi++) {
        #pragma unroll
        for (int rr = 0; rr < 2; rr++) {
            const int m = m0 + warpM + mi * 16 + lr + rr * 8;
            #pragma unroll
            for (int ni = 0; ni < 4; ni++) {
                const int n = n0 + warpN + ni * 8 + lc * 2;
                float2 vv;
                vv.x = acc[mi][ni][rr * 2 + 0] + bias[n];
                vv.y = acc[mi][ni][rr * 2 + 1] + bias[n + 1];
                if (out_mode == 0) {
                    *(float2*)(out + (size_t)m * C_ + n) = vv;
                } else {
                    const int b = m >> 10, t = m & (T_ - 1);
                    const int h = n >> 6,  d0 = n & (D_ - 1);
                    *(float2*)(out + (((size_t)(b * H_ + h)) * T_ + t) * D_ + d0) = vv;
                }
            }
        }
    }
}

__global__ void __launch_bounds__(256)
proj_tc_kernel(const float* __restrict__ q, const float* __restrict__ k,
               const float* __restrict__ v, const float* __restrict__ Wk,
               const float* __restrict__ bk)
{
    const float* X = (blockIdx.z == 0) ? q : (blockIdx.z == 1) ? k : v;
    float* O = (blockIdx.z == 0) ? g_qp : (blockIdx.z == 1) ? g_kp : g_vp;
    gemm_tc(X, Wk, bk, O, 1);
}

__global__ void __launch_bounds__(256)
outproj_tc_kernel(const float* __restrict__ Wc, const float* __restrict__ bc,
                  float* __restrict__ out)
{
    gemm_tc(g_y, Wc, bc, out, 0);
}

// ---------------------------------------------------------------------------
// Tensor-core causal flash attention (tf32 mma.sync, FA2-style).
// CTA: 64 q-rows of one (b,h); 4 warps x 16 rows. K/V double-buffered SMEM.
// Softmax in registers; P accum -> A-fragment via intra-quad shuffles.
// ---------------------------------------------------------------------------
#define KSTR 68                         // K tile row stride (floats)
#define VSTR 72                         // V tile row stride (floats)
#define ATT_SMEM_BYTES ((2*64*KSTR + 2*64*VSTR) * 4)   // 71680

__global__ void __launch_bounds__(128)
attn_tc_kernel()
{
    extern __shared__ float sf[];
    float* Kb[2] = { sf,             sf + 64*KSTR };
    float* Vb[2] = { sf + 2*64*KSTR, sf + 2*64*KSTR + 64*VSTR };

    const int qt   = 15 - blockIdx.x;       // heavy tiles first
    const int bh   = blockIdx.y;             // 0..31
    const int tid  = threadIdx.x;
    const int w    = tid >> 5;                // 0..3
    const int lane = tid & 31;
    const int g    = lane >> 2;               // 0..7
    const int lc   = lane & 3;                // 0..3

    const float* Qg = g_qp + (size_t)bh * T_ * D_;
    const float* Kg = g_kp + (size_t)bh * T_ * D_;
    const float* Vg = g_vp + (size_t)bh * T_ * D_;

    const int row0 = qt * 64 + w * 16 + g;    // global t of c0/c1 rows
    const int row1 = row0 + 8;

    // Q fragments: pre-scaled by 1/sqrt(D)=0.125, tf32, in registers
    uint32_t qf[8][4];
    #pragma unroll
    for (int ks = 0; ks < 8; ks++) {
        qf[ks][0] = f2tf32(Qg[(size_t)row0 * D_ + ks*8 + lc]     * 0.125f);
        qf[ks][1] = f2tf32(Qg[(size_t)row1 * D_ + ks*8 + lc]     * 0.125f);
        qf[ks][2] = f2tf32(Qg[(size_t)row0 * D_ + ks*8 + lc + 4] * 0.125f);
        qf[ks][3] = f2tf32(Qg[(size_t)row1 * D_ + ks*8 + lc + 4] * 0.125f);
    }

    float o[8][4];
    #pragma unroll
    for (int ni = 0; ni < 8; ni++)
        #pragma unroll
        for (int e = 0; e < 4; e++) o[ni][e] = 0.f;
    float m0 = -1e30f, m1 = -1e30f, l0 = 0.f, l1 = 0.f;

    auto load_kv = [&](int kt, int s) {
        const uint32_t kb = smem_u32(Kb[s]);
        const uint32_t vb = smem_u32(Vb[s]);
        #pragma unroll
        for (int i = 0; i < 8; i++) {
            int idx = tid + i * 128;          // 0..1023
            int r   = idx >> 4;               // 0..63
            int c4  = idx & 15;               // 0..15
            const float* gk = Kg + (size_t)(kt*64 + r) * D_ + c4 * 4;
            asm volatile("cp.async.cg.shared.global [%0], [%1], 16;"
                         :: "r"(kb + (uint32_t)(r*KSTR + c4*4)*4), "l"(gk));
            const float* gv = Vg + (size_t)(kt*64 + r) * D_ + c4 * 4;
            asm volatile("cp.async.cg.shared.global [%0], [%1], 16;"
                         :: "r"(vb + (uint32_t)(r*VSTR + c4*4)*4), "l"(gv));
        }
        asm volatile("cp.async.commit_group;" ::: "memory");
    };

    load_kv(0, 0);
    const int nk = qt + 1;

    for (int kt = 0; kt < nk; kt++) {
        const int s = kt & 1;
        asm volatile("cp.async.wait_group 0;" ::: "memory");
        __syncthreads();                  // data visible + prev compute done
        if (kt + 1 < nk) load_kv(kt + 1, s ^ 1);

        const float* K = Kb[s];
        const float* V = Vb[s];

        // ---- S = Q K^T (accum p[ni][4]) ----
        float p[8][4];
        #pragma unroll
        for (int ni = 0; ni < 8; ni++)
            #pragma unroll
            for (int e = 0; e < 4; e++) p[ni][e] = 0.f;

        #pragma unroll
        for (int ks = 0; ks < 8; ks++) {
            #pragma unroll
            for (int ni = 0; ni < 8; ni++) {
                const float* kp = K + (ni*8 + g) * KSTR + ks*8 + lc;
                uint32_t b0 = f2tf32(kp[0]);
                uint32_t b1 = f2tf32(kp[4]);
                mma_tf32(p[ni], qf[ks][0], qf[ks][1], qf[ks][2], qf[ks][3], b0, b1);
            }
        }

        // ---- causal mask on diagonal tile ----
        if (kt == qt) {
            #pragma unroll
            for (int ni = 0; ni < 8; ni++) {
                const int c = kt*64 + ni*8 + lc*2;
                if (c     > row0) p[ni][0] = -1e30f;
                if (c + 1 > row0) p[ni][1] = -1e30f;
                if (c     > row1) p[ni][2] = -1e30f;
                if (c + 1 > row1) p[ni][3] = -1e30f;
            }
        }

        // ---- online softmax (rows row0, row1; reduce over quad lanes) ----
        float rm0 = -1e30f, rm1 = -1e30f;
        #pragma unroll
        for (int ni = 0; ni < 8; ni++) {
            rm0 = fmaxf(rm0, fmaxf(p[ni][0], p[ni][1]));
            rm1 = fmaxf(rm1, fmaxf(p[ni][2], p[ni][3]));
        }
        rm0 = fmaxf(rm0, __shfl_xor_sync(0xffffffffu, rm0, 1));
        rm0 = fmaxf(rm0, __shfl_xor_sync(0xffffffffu, rm0, 2));
        rm1 = fmaxf(rm1, __shfl_xor_sync(0xffffffffu, rm1, 1));
        rm1 = fmaxf(rm1, __shfl_xor_sync(0xffffffffu, rm1, 2));

        const float mn0 = fmaxf(m0, rm0);
        const float mn1 = fmaxf(m1, rm1);
        const float corr0 = __expf(m0 - mn0);
        const float corr1 = __expf(m1 - mn1);
        m0 = mn0; m1 = mn1;

        float rs0 = 0.f, rs1 = 0.f;
        #pragma unroll
        for (int ni = 0; ni < 8; ni++) {
            p[ni][0] = __expf(p[ni][0] - m0);
            p[ni][1] = __expf(p[ni][1] - m0);
            p[ni][2] = __expf(p[ni][2] - m1);
            p[ni][3] = __expf(p[ni][3] - m1);
            rs0 += p[ni][0] + p[ni][1];
            rs1 += p[ni][2] + p[ni][3];
        }
        rs0 += __shfl_xor_sync(0xffffffffu, rs0, 1);
        rs0 += __shfl_xor_sync(0xffffffffu, rs0, 2);
        rs1 += __shfl_xor_sync(0xffffffffu, rs1, 1);
        rs1 += __shfl_xor_sync(0xffffffffu, rs1, 2);
        l0 = l0 * corr0 + rs0;
        l1 = l1 * corr1 + rs1;

        #pragma unroll
        for (int ni = 0; ni < 8; ni++) {
            o[ni][0] *= corr0; o[ni][1] *= corr0;
            o[ni][2] *= corr1; o[ni][3] *= corr1;
        }

        // ---- O += P V : convert P accum -> A frags via quad shuffles ----
        const int src_lo = (lane & ~3) | (lc >> 1);
        const int src_hi = src_lo + 2;
        #pragma unroll
        for (int ks = 0; ks < 8; ks++) {
            float v00 = __shfl_sync(0xffffffffu, p[ks][0], src_lo);
            float v01 = __shfl_sync(0xffffffffu, p[ks][1], src_lo);
            float v20 = __shfl_sync(0xffffffffu, p[ks][2], src_lo);
            float v21 = __shfl_sync(0xffffffffu, p[ks][3], src_lo);
            float w00 = __shfl_sync(0xffffffffu, p[ks][0], src_hi);
            float w01 = __shfl_sync(0xffffffffu, p[ks][1], src_hi);
            float w20 = __shfl_sync(0xffffffffu, p[ks][2], src_hi);
            float w21 = __shfl_sync(0xffffffffu, p[ks][3], src_hi);
            const bool oddc = (lc & 1);
            uint32_t a0 = f2tf32(oddc ? v01 : v00);   // (row0, k=ks*8+lc)
            uint32_t a1 = f2tf32(oddc ? v21 : v20);   // (row1, k)
            uint32_t a2 = f2tf32(oddc ? w01 : w00);   // (row0, k+4)
            uint32_t a3 = f2tf32(oddc ? w21 : w20);   // (row1, k+4)
            #pragma unroll
            for (int ni = 0; ni < 8; ni++) {
                uint32_t b0 = f2tf32(V[(ks*8 + lc)     * VSTR + ni*8 + g]);
                uint32_t b1 = f2tf32(V[(ks*8 + lc + 4) * VSTR + ni*8 + g]);
                mma_tf32(o[ni], a0, a1, a2, a3, b0, b1);
            }
        }
    }

    // ---- epilogue: y[b, t, h*64 + d] = O / l ----
    const float inv0 = 1.0f / l0;
    const float inv1 = 1.0f / l1;
    const int b = bh >> 4, h = bh & 15;
    float* y0 = g_y + ((size_t)(b * T_ + row0)) * C_ + h * D_;
    float* y1 = g_y + ((size_t)(b * T_ + row1)) * C_ + h * D_;
    #pragma unroll
    for (int ni = 0; ni < 8; ni++) {
        const int d = ni*8 + lc*2;
        float2 v0 = { o[ni][0] * inv0, o[ni][1] * inv0 };
        float2 v1 = { o[ni][2] * inv1, o[ni][3] * inv1 };
        *(float2*)(y0 + d) = v0;
        *(float2*)(y1 + d) = v1;
    }
}

// ---------------------------------------------------------------------------
extern "C" void kernel_launch(void* const* d_in, const int* in_sizes, int n_in,
                              void* d_out, int out_size)
{
    const float* q  = (const float*)d_in[0];
    const float* k  = (const float*)d_in[1];
    const float* v  = (const float*)d_in[2];
    // d_in[3] = causal mask (unused: causality handled analytically)
    const float* Wk = (const float*)d_in[4];
    const float* bk = (const float*)d_in[5];
    const float* Wc = (const float*)d_in[6];
    const float* bc = (const float*)d_in[7];
    float* out = (float*)d_out;

    cudaFuncSetAttribute(proj_tc_kernel,
                         cudaFuncAttributeMaxDynamicSharedMemorySize, SMEM_GEMM_BYTES);
    cudaFuncSetAttribute(outproj_tc_kernel,
                         cudaFuncAttributeMaxDynamicSharedMemorySize, SMEM_GEMM_BYTES);
    cudaFuncSetAttribute(attn_tc_kernel,
                         cudaFuncAttributeMaxDynamicSharedMemorySize, ATT_SMEM_BYTES);

    // 1) fused Q/K/V projection (tf32 mma.sync) -> [B,H,T,D] scratch
    proj_tc_kernel<<<dim3(C_/BN, M_/BM, 3), 256, SMEM_GEMM_BYTES>>>(q, k, v, Wk, bk);

    // 2) tensor-core causal flash attention -> g_y [B*T, C]
    attn_tc_kernel<<<dim3(T_/64, B_*H_), 128, ATT_SMEM_BYTES>>>();

    // 3) output projection (tf32 mma.sync) -> d_out
    outproj_tc_kernel<<<dim3(C_/BN, M_/BM, 1), 256, SMEM_GEMM_BYTES>>>(Wc, bc, out);
}

// round 6
// speedup vs baseline: 6.6441x; 2.1619x over previous
#include <cuda_runtime.h>
#include <cuda_fp16.h>
#include <cstdint>

#define B_ 2
#define T_ 1024
#define C_ 1024
#define H_ 16
#define D_ 64
#define M_ (B_*T_)   // 2048 rows

// fp16 scratch (static device globals: allocation-free per harness rules)
__device__ __half g_qh [(size_t)M_*C_];       // fp16 copies of inputs
__device__ __half g_kh [(size_t)M_*C_];
__device__ __half g_vh [(size_t)M_*C_];
__device__ __half g_Wkh[(size_t)C_*C_];
__device__ __half g_Wch[(size_t)C_*C_];
__device__ __half g_qp [(size_t)B_*H_*T_*D_]; // projected, [B,H,T,D] (q pre-scaled)
__device__ __half g_kp [(size_t)B_*H_*T_*D_];
__device__ __half g_vp [(size_t)B_*H_*T_*D_];
__device__ __half g_y  [(size_t)M_*C_];       // attention output, [B*T, C]

__device__ __forceinline__ uint32_t smem_u32(const void* p) {
    uint32_t a;
    asm("{ .reg .u64 t; cvta.to.shared.u64 t, %1; cvt.u32.u64 %0, t; }"
        : "=r"(a) : "l"(p));
    return a;
}

__device__ __forceinline__ uint32_t packh2(float a, float b) {
    __half2 h = __floats2half2_rn(a, b);
    return *(uint32_t*)&h;
}

__device__ __forceinline__ void mma_f16(
    float* c, uint32_t a0, uint32_t a1, uint32_t a2, uint32_t a3,
    uint32_t b0, uint32_t b1)
{
    asm volatile(
        "mma.sync.aligned.m16n8k16.row.col.f32.f16.f16.f32 "
        "{%0,%1,%2,%3}, {%4,%5,%6,%7}, {%8,%9}, {%0,%1,%2,%3};"
        : "+f"(c[0]), "+f"(c[1]), "+f"(c[2]), "+f"(c[3])
        : "r"(a0), "r"(a1), "r"(a2), "r"(a3), "r"(b0), "r"(b1));
}

__device__ __forceinline__ void ldmat4(uint32_t* r, uint32_t addr) {
    asm volatile("ldmatrix.sync.aligned.m8n8.x4.shared.b16 {%0,%1,%2,%3}, [%4];"
        : "=r"(r[0]), "=r"(r[1]), "=r"(r[2]), "=r"(r[3]) : "r"(addr));
}
__device__ __forceinline__ void ldmat4t(uint32_t* r, uint32_t addr) {
    asm volatile("ldmatrix.sync.aligned.m8n8.x4.trans.shared.b16 {%0,%1,%2,%3}, [%4];"
        : "=r"(r[0]), "=r"(r[1]), "=r"(r[2]), "=r"(r[3]) : "r"(addr));
}

// ---------------------------------------------------------------------------
// fp32 -> fp16 conversion of all GEMM inputs (one kernel, z picks array)
// ---------------------------------------------------------------------------
__global__ void __launch_bounds__(256)
cvt_kernel(const float* __restrict__ q, const float* __restrict__ k,
           const float* __restrict__ v, const float* __restrict__ Wk,
           const float* __restrict__ Wc)
{
    const float* src; __half* dst; int n;
    switch (blockIdx.y) {
        case 0: src = q;  dst = g_qh;  n = M_*C_; break;
        case 1: src = k;  dst = g_kh;  n = M_*C_; break;
        case 2: src = v;  dst = g_vh;  n = M_*C_; break;
        case 3: src = Wk; dst = g_Wkh; n = C_*C_; break;
        default: src = Wc; dst = g_Wch; n = C_*C_; break;
    }
    int i = (blockIdx.x * 256 + threadIdx.x) * 4;
    if (i < n) {
        float4 f = *(const float4*)(src + i);
        __half2 h0 = __floats2half2_rn(f.x, f.y);
        __half2 h1 = __floats2half2_rn(f.z, f.w);
        *(__half2*)(dst + i)     = h0;
        *(__half2*)(dst + i + 2) = h1;
    }
}

// ---------------------------------------------------------------------------
// fp16 mma.sync GEMM: out = Xh[M,1024] @ Wh[1024,1024]^T + bias[1024]
// CTA 128x128, BK=64, 256 threads (8 warps 2x4), warp tile 64x32, ldmatrix.
// out_mode 0: fp32 [M,N]; 1: fp16 scatter [B,H,T,D] (*oscale after bias).
// ---------------------------------------------------------------------------
#define BKg 64
#define GSTR 72                                   // halves per SMEM row (pad 8)
#define GBUF (128 * GSTR)                         // halves per tile buffer
#define SMEM_GEMM_BYTES (4 * GBUF * 2)            // 73728

__device__ __forceinline__ void gemm_h(
    const __half* __restrict__ X, const __half* __restrict__ W,
    const float* __restrict__ bias, void* __restrict__ out,
    int out_mode, float oscale)
{
    extern __shared__ __half smh[];
    __half* Abuf[2] = { smh,          smh + GBUF };
    __half* Bbuf[2] = { smh + 2*GBUF, smh + 3*GBUF };

    const int tid  = threadIdx.x;
    const int wid  = tid >> 5;
    const int lane = tid & 31;
    const int warpM = (wid >> 2) * 64;
    const int warpN = (wid & 3) * 32;
    const int m0 = blockIdx.y * 128;
    const int n0 = blockIdx.x * 128;
    const int lr = lane >> 2;
    const int lc = lane & 3;

    float acc[4][4][4];
    #pragma unroll
    for (int i = 0; i < 4; i++)
        #pragma unroll
        for (int j = 0; j < 4; j++)
            #pragma unroll
            for (int e = 0; e < 4; e++) acc[i][j][e] = 0.f;

    auto load_chunk = [&](int ch, int s) {
        const uint32_t aB = smem_u32(Abuf[s]);
        const uint32_t bB = smem_u32(Bbuf[s]);
        #pragma unroll
        for (int i = 0; i < 4; i++) {
            int idx = tid + i * 256;             // 0..1023
            int r   = idx >> 3;                  // 0..127
            int c16 = idx & 7;                   // 16B column
            uint32_t soff = (uint32_t)(r * GSTR + c16 * 8) * 2;
            const __half* gA = X + (size_t)(m0 + r) * C_ + ch * BKg + c16 * 8;
            asm volatile("cp.async.cg.shared.global [%0], [%1], 16;"
                         :: "r"(aB + soff), "l"(gA));
            const __half* gB = W + (size_t)(n0 + r) * C_ + ch * BKg + c16 * 8;
            asm volatile("cp.async.cg.shared.global [%0], [%1], 16;"
                         :: "r"(bB + soff), "l"(gB));
        }
        asm volatile("cp.async.commit_group;" ::: "memory");
    };

    const int NCH = C_ / BKg;                    // 16
    load_chunk(0, 0);

    for (int ch = 0; ch < NCH; ch++) {
        const int s = ch & 1;
        if (ch + 1 < NCH) load_chunk(ch + 1, s ^ 1);
        if (ch + 1 < NCH)
            asm volatile("cp.async.wait_group 1;" ::: "memory");
        else
            asm volatile("cp.async.wait_group 0;" ::: "memory");
        __syncthreads();

        const uint32_t aB = smem_u32(Abuf[s]);
        const uint32_t bB = smem_u32(Bbuf[s]);

        #pragma unroll
        for (int kk = 0; kk < BKg; kk += 16) {
            uint32_t af[4][4], bf[2][4];
            #pragma unroll
            for (int mi = 0; mi < 4; mi++) {
                int row = warpM + mi * 16 + (lane & 15);
                int col = kk + (lane >> 4) * 8;
                ldmat4(af[mi], aB + (uint32_t)(row * GSTR + col) * 2);
            }
            #pragma unroll
            for (int np = 0; np < 2; np++) {
                int row = warpN + np * 16 + (lane & 7) + ((lane >> 4) & 1) * 8;
                int col = kk + ((lane >> 3) & 1) * 8;
                ldmat4(bf[np], bB + (uint32_t)(row * GSTR + col) * 2);
            }
            #pragma unroll
            for (int mi = 0; mi < 4; mi++)
                #pragma unroll
                for (int ni = 0; ni < 4; ni++)
                    mma_f16(acc[mi][ni],
                            af[mi][0], af[mi][1], af[mi][2], af[mi][3],
                            bf[ni >> 1][(ni & 1) * 2], bf[ni >> 1][(ni & 1) * 2 + 1]);
        }
        __syncthreads();
    }

    #pragma unroll
    for (int mi = 0; mi < 4; mi++) {
        #pragma unroll
        for (int rr = 0; rr < 2; rr++) {
            const int m = m0 + warpM + mi * 16 + lr + rr * 8;
            #pragma unroll
            for (int ni = 0; ni < 4; ni++) {
                const int n = n0 + warpN + ni * 8 + lc * 2;
                float vx = (acc[mi][ni][rr*2+0] + bias[n])     * oscale;
                float vy = (acc[mi][ni][rr*2+1] + bias[n + 1]) * oscale;
                if (out_mode == 0) {
                    float2 vv = { vx, vy };
                    *(float2*)((float*)out + (size_t)m * C_ + n) = vv;
                } else {
                    const int b = m >> 10, t = m & (T_ - 1);
                    const int h = n >> 6,  d0 = n & (D_ - 1);
                    *(__half2*)((__half*)out +
                        (((size_t)(b * H_ + h)) * T_ + t) * D_ + d0) =
                        __floats2half2_rn(vx, vy);
                }
            }
        }
    }
}

__global__ void __launch_bounds__(256)
proj_h_kernel(const float* __restrict__ bk)
{
    const __half* X = (blockIdx.z == 0) ? g_qh : (blockIdx.z == 1) ? g_kh : g_vh;
    __half* O = (blockIdx.z == 0) ? g_qp : (blockIdx.z == 1) ? g_kp : g_vp;
    const float sc = (blockIdx.z == 0) ? 0.125f : 1.0f;   // fold 1/sqrt(D) into Q
    gemm_h(X, g_Wkh, bk, O, 1, sc);
}

__global__ void __launch_bounds__(256)
outproj_h_kernel(const float* __restrict__ bc, float* __restrict__ out)
{
    gemm_h(g_y, g_Wch, bc, out, 0, 1.0f);
}

// ---------------------------------------------------------------------------
// fp16 tensor-core causal flash attention.
// CTA: 64 q-rows of one (b,h); 4 warps x 16 rows; K/V double-buffered SMEM.
// Softmax fp32 in registers; S-accum layout == A-frag layout -> shuffle-free P.
// ---------------------------------------------------------------------------
#define ASTR 72                                   // halves per SMEM row

__global__ void __launch_bounds__(128)
attn_h_kernel()
{
    __shared__ __half sQ[64 * ASTR];
    __shared__ __half sK[2][64 * ASTR];
    __shared__ __half sV[2][64 * ASTR];

    const int qt   = 15 - blockIdx.x;             // heavy tiles first
    const int bh   = blockIdx.y;                   // 0..31
    const int tid  = threadIdx.x;
    const int w    = tid >> 5;
    const int lane = tid & 31;
    const int g    = lane >> 2;
    const int lc   = lane & 3;

    const __half* Qg = g_qp + (size_t)bh * T_ * D_;
    const __half* Kg = g_kp + (size_t)bh * T_ * D_;
    const __half* Vg = g_vp + (size_t)bh * T_ * D_;

    const int row0 = qt * 64 + w * 16 + g;
    const int row1 = row0 + 8;

    auto load_tile = [&](const __half* src, __half* dstTile, int rbase) {
        const uint32_t db = smem_u32(dstTile);
        #pragma unroll
        for (int i = 0; i < 4; i++) {
            int idx = tid + i * 128;               // 0..511
            int r   = idx >> 3;                    // 0..63
            int c16 = idx & 7;
            const __half* gp = src + (size_t)(rbase + r) * D_ + c16 * 8;
            asm volatile("cp.async.cg.shared.global [%0], [%1], 16;"
                         :: "r"(db + (uint32_t)(r * ASTR + c16 * 8) * 2), "l"(gp));
        }
    };

    // group 0: Q tile + KV tile 0
    load_tile(Qg, sQ, qt * 64);
    load_tile(Kg, sK[0], 0);
    load_tile(Vg, sV[0], 0);
    asm volatile("cp.async.commit_group;" ::: "memory");

    float o[8][4];
    #pragma unroll
    for (int ni = 0; ni < 8; ni++)
        #pragma unroll
        for (int e = 0; e < 4; e++) o[ni][e] = 0.f;
    float m0 = -1e30f, m1 = -1e30f, l0 = 0.f, l1 = 0.f;

    uint32_t qf[4][4];
    const int nk = qt + 1;

    for (int kt = 0; kt < nk; kt++) {
        const int s = kt & 1;
        asm volatile("cp.async.wait_group 0;" ::: "memory");
        __syncthreads();                           // data ready + prev compute done
        if (kt + 1 < nk) {
            load_tile(Kg, sK[s ^ 1], (kt + 1) * 64);
            load_tile(Vg, sV[s ^ 1], (kt + 1) * 64);
            asm volatile("cp.async.commit_group;" ::: "memory");
        }
        if (kt == 0) {
            const uint32_t qb = smem_u32(sQ);
            #pragma unroll
            for (int ks = 0; ks < 4; ks++) {
                int row = w * 16 + (lane & 15);
                int col = ks * 16 + (lane >> 4) * 8;
                ldmat4(qf[ks], qb + (uint32_t)(row * ASTR + col) * 2);
            }
        }

        const uint32_t kb = smem_u32(sK[s]);
        const uint32_t vb = smem_u32(sV[s]);

        // ---- S = Q K^T ----
        float p[8][4];
        #pragma unroll
        for (int ni = 0; ni < 8; ni++)
            #pragma unroll
            for (int e = 0; e < 4; e++) p[ni][e] = 0.f;

        #pragma unroll
        for (int ks = 0; ks < 4; ks++) {
            #pragma unroll
            for (int np = 0; np < 4; np++) {
                uint32_t kf[4];
                int row = np * 16 + (lane & 7) + ((lane >> 4) & 1) * 8;
                int col = ks * 16 + ((lane >> 3) & 1) * 8;
                ldmat4(kf, kb + (uint32_t)(row * ASTR + col) * 2);
                mma_f16(p[np*2],   qf[ks][0], qf[ks][1], qf[ks][2], qf[ks][3], kf[0], kf[1]);
                mma_f16(p[np*2+1], qf[ks][0], qf[ks][1], qf[ks][2], qf[ks][3], kf[2], kf[3]);
            }
        }

        // ---- causal mask on diagonal tile ----
        if (kt == qt) {
            #pragma unroll
            for (int ni = 0; ni < 8; ni++) {
                const int c = kt * 64 + ni * 8 + lc * 2;
                if (c     > row0) p[ni][0] = -1e30f;
                if (c + 1 > row0) p[ni][1] = -1e30f;
                if (c     > row1) p[ni][2] = -1e30f;
                if (c + 1 > row1) p[ni][3] = -1e30f;
            }
        }

        // ---- online softmax ----
        float rm0 = -1e30f, rm1 = -1e30f;
        #pragma unroll
        for (int ni = 0; ni < 8; ni++) {
            rm0 = fmaxf(rm0, fmaxf(p[ni][0], p[ni][1]));
            rm1 = fmaxf(rm1, fmaxf(p[ni][2], p[ni][3]));
        }
        rm0 = fmaxf(rm0, __shfl_xor_sync(0xffffffffu, rm0, 1));
        rm0 = fmaxf(rm0, __shfl_xor_sync(0xffffffffu, rm0, 2));
        rm1 = fmaxf(rm1, __shfl_xor_sync(0xffffffffu, rm1, 1));
        rm1 = fmaxf(rm1, __shfl_xor_sync(0xffffffffu, rm1, 2));

        const float mn0 = fmaxf(m0, rm0);
        const float mn1 = fmaxf(m1, rm1);
        const float corr0 = __expf(m0 - mn0);
        const float corr1 = __expf(m1 - mn1);
        m0 = mn0; m1 = mn1;

        float rs0 = 0.f, rs1 = 0.f;
        #pragma unroll
        for (int ni = 0; ni < 8; ni++) {
            p[ni][0] = __expf(p[ni][0] - m0);
            p[ni][1] = __expf(p[ni][1] - m0);
            p[ni][2] = __expf(p[ni][2] - m1);
            p[ni][3] = __expf(p[ni][3] - m1);
            rs0 += p[ni][0] + p[ni][1];
            rs1 += p[ni][2] + p[ni][3];
        }
        rs0 += __shfl_xor_sync(0xffffffffu, rs0, 1);
        rs0 += __shfl_xor_sync(0xffffffffu, rs0, 2);
        rs1 += __shfl_xor_sync(0xffffffffu, rs1, 1);
        rs1 += __shfl_xor_sync(0xffffffffu, rs1, 2);
        l0 = l0 * corr0 + rs0;
        l1 = l1 * corr1 + rs1;

        #pragma unroll
        for (int ni = 0; ni < 8; ni++) {
            o[ni][0] *= corr0; o[ni][1] *= corr0;
            o[ni][2] *= corr1; o[ni][3] *= corr1;
        }

        // ---- O += P V : accum layout == A-frag layout, just pack to fp16 ----
        #pragma unroll
        for (int ks = 0; ks < 4; ks++) {
            uint32_t a0 = packh2(p[2*ks][0],   p[2*ks][1]);
            uint32_t a1 = packh2(p[2*ks][2],   p[2*ks][3]);
            uint32_t a2 = packh2(p[2*ks+1][0], p[2*ks+1][1]);
            uint32_t a3 = packh2(p[2*ks+1][2], p[2*ks+1][3]);
            #pragma unroll
            for (int np = 0; np < 4; np++) {
                uint32_t vf[4];
                int row = ks * 16 + (lane & 7) + ((lane >> 3) & 1) * 8;
                int col = np * 16 + ((lane >> 4) & 1) * 8;
                ldmat4t(vf, vb + (uint32_t)(row * ASTR + col) * 2);
                mma_f16(o[np*2],   a0, a1, a2, a3, vf[0], vf[1]);
                mma_f16(o[np*2+1], a0, a1, a2, a3, vf[2], vf[3]);
            }
        }
    }

    // ---- epilogue: y[b, t, h*64 + d] = O / l (fp16) ----
    const float inv0 = 1.0f / l0;
    const float inv1 = 1.0f / l1;
    const int b = bh >> 4, h = bh & 15;
    __half* y0 = g_y + ((size_t)(b * T_ + row0)) * C_ + h * D_;
    __half* y1 = g_y + ((size_t)(b * T_ + row1)) * C_ + h * D_;
    #pragma unroll
    for (int ni = 0; ni < 8; ni++) {
        const int d = ni * 8 + lc * 2;
        *(__half2*)(y0 + d) = __floats2half2_rn(o[ni][0] * inv0, o[ni][1] * inv0);
        *(__half2*)(y1 + d) = __floats2half2_rn(o[ni][2] * inv1, o[ni][3] * inv1);
    }
}

// ---------------------------------------------------------------------------
extern "C" void kernel_launch(void* const* d_in, const int* in_sizes, int n_in,
                              void* d_out, int out_size)
{
    const float* q  = (const float*)d_in[0];
    const float* k  = (const float*)d_in[1];
    const float* v  = (const float*)d_in[2];
    // d_in[3] = causal mask (unused: causality handled analytically)
    const float* Wk = (const float*)d_in[4];
    const float* bk = (const float*)d_in[5];
    const float* Wc = (const float*)d_in[6];
    const float* bc = (const float*)d_in[7];
    float* out = (float*)d_out;

    cudaFuncSetAttribute(proj_h_kernel,
                         cudaFuncAttributeMaxDynamicSharedMemorySize, SMEM_GEMM_BYTES);
    cudaFuncSetAttribute(outproj_h_kernel,
                         cudaFuncAttributeMaxDynamicSharedMemorySize, SMEM_GEMM_BYTES);

    // 0) fp32 -> fp16 conversion of all GEMM operands
    cvt_kernel<<<dim3((M_*C_)/(256*4), 5), 256>>>(q, k, v, Wk, Wc);

    // 1) fused Q/K/V projection (fp16 mma.sync) -> [B,H,T,D] fp16 scratch
    proj_h_kernel<<<dim3(8, 16, 3), 256, SMEM_GEMM_BYTES>>>(bk);

    // 2) fp16 tensor-core causal flash attention -> g_y [B*T, C] fp16
    attn_h_kernel<<<dim3(16, 32), 128>>>();

    // 3) output projection (fp16 mma.sync) -> fp32 d_out
    outproj_h_kernel<<<dim3(8, 16, 1), 256, SMEM_GEMM_BYTES>>>(bc, out);
}

// round 7
// speedup vs baseline: 7.2656x; 1.0936x over previous
#include <cuda_runtime.h>
#include <cuda_fp16.h>
#include <cstdint>

#define B_ 2
#define T_ 1024
#define C_ 1024
#define H_ 16
#define D_ 64
#define M_ (B_*T_)   // 2048 rows

// fp16 scratch (static device globals: allocation-free per harness rules)
__device__ __half g_qh [(size_t)M_*C_];
__device__ __half g_kh [(size_t)M_*C_];
__device__ __half g_vh [(size_t)M_*C_];
__device__ __half g_Wkh[(size_t)C_*C_];
__device__ __half g_Wch[(size_t)C_*C_];
__device__ __half g_qp [(size_t)B_*H_*T_*D_]; // q pre-scaled by 0.125*log2(e)
__device__ __half g_kp [(size_t)B_*H_*T_*D_];
__device__ __half g_vp [(size_t)B_*H_*T_*D_];
__device__ __half g_y  [(size_t)M_*C_];

__device__ __forceinline__ uint32_t smem_u32(const void* p) {
    uint32_t a;
    asm("{ .reg .u64 t; cvta.to.shared.u64 t, %1; cvt.u32.u64 %0, t; }"
        : "=r"(a) : "l"(p));
    return a;
}

__device__ __forceinline__ uint32_t packh2(float a, float b) {
    __half2 h = __floats2half2_rn(a, b);
    return *(uint32_t*)&h;
}

__device__ __forceinline__ void mma_f16(
    float* c, uint32_t a0, uint32_t a1, uint32_t a2, uint32_t a3,
    uint32_t b0, uint32_t b1)
{
    asm volatile(
        "mma.sync.aligned.m16n8k16.row.col.f32.f16.f16.f32 "
        "{%0,%1,%2,%3}, {%4,%5,%6,%7}, {%8,%9}, {%0,%1,%2,%3};"
        : "+f"(c[0]), "+f"(c[1]), "+f"(c[2]), "+f"(c[3])
        : "r"(a0), "r"(a1), "r"(a2), "r"(a3), "r"(b0), "r"(b1));
}

__device__ __forceinline__ void ldmat4(uint32_t* r, uint32_t addr) {
    asm volatile("ldmatrix.sync.aligned.m8n8.x4.shared.b16 {%0,%1,%2,%3}, [%4];"
        : "=r"(r[0]), "=r"(r[1]), "=r"(r[2]), "=r"(r[3]) : "r"(addr));
}
__device__ __forceinline__ void ldmat4t(uint32_t* r, uint32_t addr) {
    asm volatile("ldmatrix.sync.aligned.m8n8.x4.trans.shared.b16 {%0,%1,%2,%3}, [%4];"
        : "=r"(r[0]), "=r"(r[1]), "=r"(r[2]), "=r"(r[3]) : "r"(addr));
}

// ---------------------------------------------------------------------------
// fp32 -> fp16 conversion of all GEMM inputs
// ---------------------------------------------------------------------------
__global__ void __launch_bounds__(256)
cvt_kernel(const float* __restrict__ q, const float* __restrict__ k,
           const float* __restrict__ v, const float* __restrict__ Wk,
           const float* __restrict__ Wc)
{
    const float* src; __half* dst; int n;
    switch (blockIdx.y) {
        case 0: src = q;  dst = g_qh;  n = M_*C_; break;
        case 1: src = k;  dst = g_kh;  n = M_*C_; break;
        case 2: src = v;  dst = g_vh;  n = M_*C_; break;
        case 3: src = Wk; dst = g_Wkh; n = C_*C_; break;
        default: src = Wc; dst = g_Wch; n = C_*C_; break;
    }
    int i = (blockIdx.x * 256 + threadIdx.x) * 4;
    if (i < n) {
        float4 f = *(const float4*)(src + i);
        *(__half2*)(dst + i)     = __floats2half2_rn(f.x, f.y);
        *(__half2*)(dst + i + 2) = __floats2half2_rn(f.z, f.w);
    }
}

// ---------------------------------------------------------------------------
// fp16 mma.sync GEMM: out = Xh[M,1024] @ Wh[1024,1024]^T + bias[1024]
// CTA 128x128, BK=32, 4-stage cp.async pipeline, swizzled SMEM (64B rows),
// one __syncthreads per chunk, 2 CTAs/SM.
// ---------------------------------------------------------------------------
#define BKg 32
#define NCHg (C_/BKg)                  // 32
#define STAGE_BYTES 16384              // A(8KB) + B(8KB)
#define SMEM_GEMM_BYTES (4 * STAGE_BYTES)   // 65536

// swizzled byte offset for (row, 16B-chunk c) in a 64B-row tile
__device__ __forceinline__ uint32_t swz64(int row, int c) {
    return (uint32_t)(row * 64 + ((c ^ ((row >> 1) & 3)) << 4));
}

__device__ __forceinline__ void gemm_h(
    const __half* __restrict__ X, const __half* __restrict__ W,
    const float* __restrict__ bias, void* __restrict__ out,
    int out_mode, float oscale)
{
    extern __shared__ __half smh[];
    const uint32_t sb = smem_u32(smh);

    const int tid  = threadIdx.x;
    const int wid  = tid >> 5;
    const int lane = tid & 31;
    const int warpM = (wid >> 2) * 64;
    const int warpN = (wid & 3) * 32;
    const int m0 = blockIdx.y * 128;
    const int n0 = blockIdx.x * 128;
    const int lr = lane >> 2;
    const int lc = lane & 3;

    float acc[4][4][4];
    #pragma unroll
    for (int i = 0; i < 4; i++)
        #pragma unroll
        for (int j = 0; j < 4; j++)
            #pragma unroll
            for (int e = 0; e < 4; e++) acc[i][j][e] = 0.f;

    // loader thread mapping: idx = tid + i*256 -> row=idx>>2, chunk=idx&3
    const int ldr = tid >> 2;
    const int ldc = tid & 3;
    auto load_chunk = [&](int ch, int st) {
        const uint32_t base = sb + (uint32_t)st * STAGE_BYTES;
        #pragma unroll
        for (int i = 0; i < 2; i++) {
            const int r = ldr + i * 64;
            const uint32_t off = swz64(r, ldc);
            const __half* gA = X + (size_t)(m0 + r) * C_ + ch * BKg + ldc * 8;
            asm volatile("cp.async.cg.shared.global [%0], [%1], 16;"
                         :: "r"(base + off), "l"(gA));
            const __half* gB = W + (size_t)(n0 + r) * C_ + ch * BKg + ldc * 8;
            asm volatile("cp.async.cg.shared.global [%0], [%1], 16;"
                         :: "r"(base + 8192 + off), "l"(gB));
        }
        asm volatile("cp.async.commit_group;" ::: "memory");
    };

    load_chunk(0, 0);
    load_chunk(1, 1);

    for (int ch = 0; ch < NCHg; ch++) {
        const int st = ch & 3;
        if (ch + 2 < NCHg) {
            load_chunk(ch + 2, (ch + 2) & 3);
            asm volatile("cp.async.wait_group 2;" ::: "memory");
        } else if (ch + 1 < NCHg) {
            asm volatile("cp.async.wait_group 1;" ::: "memory");
        } else {
            asm volatile("cp.async.wait_group 0;" ::: "memory");
        }
        __syncthreads();

        const uint32_t aB = sb + (uint32_t)st * STAGE_BYTES;
        const uint32_t bB = aB + 8192;

        #pragma unroll
        for (int kk = 0; kk < BKg; kk += 16) {
            const int kc = kk >> 3;
            uint32_t af[4][4], bf[2][4];
            #pragma unroll
            for (int mi = 0; mi < 4; mi++) {
                int row = warpM + mi * 16 + (lane & 15);
                int cc  = kc + (lane >> 4);
                ldmat4(af[mi], aB + swz64(row, cc));
            }
            #pragma unroll
            for (int np = 0; np < 2; np++) {
                int row = warpN + np * 16 + (lane & 7) + ((lane >> 4) & 1) * 8;
                int cc  = kc + ((lane >> 3) & 1);
                ldmat4(bf[np], bB + swz64(row, cc));
            }
            #pragma unroll
            for (int mi = 0; mi < 4; mi++)
                #pragma unroll
                for (int ni = 0; ni < 4; ni++)
                    mma_f16(acc[mi][ni],
                            af[mi][0], af[mi][1], af[mi][2], af[mi][3],
                            bf[ni >> 1][(ni & 1) * 2], bf[ni >> 1][(ni & 1) * 2 + 1]);
        }
    }

    #pragma unroll
    for (int mi = 0; mi < 4; mi++) {
        #pragma unroll
        for (int rr = 0; rr < 2; rr++) {
            const int m = m0 + warpM + mi * 16 + lr + rr * 8;
            #pragma unroll
            for (int ni = 0; ni < 4; ni++) {
                const int n = n0 + warpN + ni * 8 + lc * 2;
                float vx = (acc[mi][ni][rr*2+0] + bias[n])     * oscale;
                float vy = (acc[mi][ni][rr*2+1] + bias[n + 1]) * oscale;
                if (out_mode == 0) {
                    float2 vv = { vx, vy };
                    *(float2*)((float*)out + (size_t)m * C_ + n) = vv;
                } else {
                    const int b = m >> 10, t = m & (T_ - 1);
                    const int h = n >> 6,  d0 = n & (D_ - 1);
                    *(__half2*)((__half*)out +
                        (((size_t)(b * H_ + h)) * T_ + t) * D_ + d0) =
                        __floats2half2_rn(vx, vy);
                }
            }
        }
    }
}

__global__ void __launch_bounds__(256, 2)
proj_h_kernel(const float* __restrict__ bk)
{
    const __half* X = (blockIdx.z == 0) ? g_qh : (blockIdx.z == 1) ? g_kh : g_vh;
    __half* O = (blockIdx.z == 0) ? g_qp : (blockIdx.z == 1) ? g_kp : g_vp;
    // fold 1/sqrt(D) * log2(e) into Q so attention works in the log2 domain
    const float sc = (blockIdx.z == 0) ? 0.125f * 1.44269504f : 1.0f;
    gemm_h(X, g_Wkh, bk, O, 1, sc);
}

__global__ void __launch_bounds__(256, 2)
outproj_h_kernel(const float* __restrict__ bc, float* __restrict__ out)
{
    gemm_h(g_y, g_Wch, bc, out, 0, 1.0f);
}

// ---------------------------------------------------------------------------
// fp16 tensor-core causal flash attention (log2-domain softmax, ex2.f16x2).
// CTA: 64 q-rows of one (b,h); 4 warps x 16 rows; K/V double-buffered.
// ---------------------------------------------------------------------------
#define ASTR 72

__global__ void __launch_bounds__(128)
attn_h_kernel()
{
    __shared__ __half sQ[64 * ASTR];
    __shared__ __half sK[2][64 * ASTR];
    __shared__ __half sV[2][64 * ASTR];

    const int qt   = 15 - blockIdx.x;             // heavy tiles first
    const int bh   = blockIdx.y;
    const int tid  = threadIdx.x;
    const int w    = tid >> 5;
    const int lane = tid & 31;
    const int g    = lane >> 2;
    const int lc   = lane & 3;

    const __half* Qg = g_qp + (size_t)bh * T_ * D_;
    const __half* Kg = g_kp + (size_t)bh * T_ * D_;
    const __half* Vg = g_vp + (size_t)bh * T_ * D_;

    const int row0 = qt * 64 + w * 16 + g;
    const int row1 = row0 + 8;

    auto load_tile = [&](const __half* src, __half* dstTile, int rbase) {
        const uint32_t db = smem_u32(dstTile);
        #pragma unroll
        for (int i = 0; i < 4; i++) {
            int idx = tid + i * 128;
            int r   = idx >> 3;
            int c16 = idx & 7;
            const __half* gp = src + (size_t)(rbase + r) * D_ + c16 * 8;
            asm volatile("cp.async.cg.shared.global [%0], [%1], 16;"
                         :: "r"(db + (uint32_t)(r * ASTR + c16 * 8) * 2), "l"(gp));
        }
    };

    load_tile(Qg, sQ, qt * 64);
    load_tile(Kg, sK[0], 0);
    load_tile(Vg, sV[0], 0);
    asm volatile("cp.async.commit_group;" ::: "memory");

    float o[8][4];
    #pragma unroll
    for (int ni = 0; ni < 8; ni++)
        #pragma unroll
        for (int e = 0; e < 4; e++) o[ni][e] = 0.f;
    float m0 = -1e30f, m1 = -1e30f, l0 = 0.f, l1 = 0.f;

    uint32_t qf[4][4];
    const int nk = qt + 1;

    for (int kt = 0; kt < nk; kt++) {
        const int s = kt & 1;
        asm volatile("cp.async.wait_group 0;" ::: "memory");
        __syncthreads();
        if (kt + 1 < nk) {
            load_tile(Kg, sK[s ^ 1], (kt + 1) * 64);
            load_tile(Vg, sV[s ^ 1], (kt + 1) * 64);
            asm volatile("cp.async.commit_group;" ::: "memory");
        }
        if (kt == 0) {
            const uint32_t qb = smem_u32(sQ);
            #pragma unroll
            for (int ks = 0; ks < 4; ks++) {
                int row = w * 16 + (lane & 15);
                int col = ks * 16 + (lane >> 4) * 8;
                ldmat4(qf[ks], qb + (uint32_t)(row * ASTR + col) * 2);
            }
        }

        const uint32_t kb = smem_u32(sK[s]);
        const uint32_t vb = smem_u32(sV[s]);

        // ---- S = Q K^T (log2-domain: Q pre-scaled by 0.125*log2e) ----
        float p[8][4];
        #pragma unroll
        for (int ni = 0; ni < 8; ni++)
            #pragma unroll
            for (int e = 0; e < 4; e++) p[ni][e] = 0.f;

        #pragma unroll
        for (int ks = 0; ks < 4; ks++) {
            #pragma unroll
            for (int np = 0; np < 4; np++) {
                uint32_t kf[4];
                int row = np * 16 + (lane & 7) + ((lane >> 4) & 1) * 8;
                int col = ks * 16 + ((lane >> 3) & 1) * 8;
                ldmat4(kf, kb + (uint32_t)(row * ASTR + col) * 2);
                mma_f16(p[np*2],   qf[ks][0], qf[ks][1], qf[ks][2], qf[ks][3], kf[0], kf[1]);
                mma_f16(p[np*2+1], qf[ks][0], qf[ks][1], qf[ks][2], qf[ks][3], kf[2], kf[3]);
            }
        }

        if (kt == qt) {
            #pragma unroll
            for (int ni = 0; ni < 8; ni++) {
                const int c = kt * 64 + ni * 8 + lc * 2;
                if (c     > row0) p[ni][0] = -1e30f;
                if (c + 1 > row0) p[ni][1] = -1e30f;
                if (c     > row1) p[ni][2] = -1e30f;
                if (c + 1 > row1) p[ni][3] = -1e30f;
            }
        }

        // ---- online softmax (base-2) ----
        float rm0 = -1e30f, rm1 = -1e30f;
        #pragma unroll
        for (int ni = 0; ni < 8; ni++) {
            rm0 = fmaxf(rm0, fmaxf(p[ni][0], p[ni][1]));
            rm1 = fmaxf(rm1, fmaxf(p[ni][2], p[ni][3]));
        }
        rm0 = fmaxf(rm0, __shfl_xor_sync(0xffffffffu, rm0, 1));
        rm0 = fmaxf(rm0, __shfl_xor_sync(0xffffffffu, rm0, 2));
        rm1 = fmaxf(rm1, __shfl_xor_sync(0xffffffffu, rm1, 1));
        rm1 = fmaxf(rm1, __shfl_xor_sync(0xffffffffu, rm1, 2));

        const float mn0 = fmaxf(m0, rm0);
        const float mn1 = fmaxf(m1, rm1);
        const float corr0 = exp2f(m0 - mn0);
        const float corr1 = exp2f(m1 - mn1);
        m0 = mn0; m1 = mn1;

        // packed exp2: pe0[ni] = exp2(p[ni][0..1]-m0), pe1[ni] = exp2(p[ni][2..3]-m1)
        uint32_t pe0[8], pe1[8];
        float rs0 = 0.f, rs1 = 0.f;
        #pragma unroll
        for (int ni = 0; ni < 8; ni++) {
            uint32_t ea = packh2(p[ni][0] - m0, p[ni][1] - m0);
            uint32_t eb = packh2(p[ni][2] - m1, p[ni][3] - m1);
            asm("ex2.approx.f16x2 %0, %0;" : "+r"(ea));
            asm("ex2.approx.f16x2 %0, %0;" : "+r"(eb));
            pe0[ni] = ea; pe1[ni] = eb;
            float2 fa = __half22float2(*(__half2*)&ea);
            float2 fb = __half22float2(*(__half2*)&eb);
            rs0 += fa.x + fa.y;
            rs1 += fb.x + fb.y;
        }
        rs0 += __shfl_xor_sync(0xffffffffu, rs0, 1);
        rs0 += __shfl_xor_sync(0xffffffffu, rs0, 2);
        rs1 += __shfl_xor_sync(0xffffffffu, rs1, 1);
        rs1 += __shfl_xor_sync(0xffffffffu, rs1, 2);
        l0 = l0 * corr0 + rs0;
        l1 = l1 * corr1 + rs1;

        #pragma unroll
        for (int ni = 0; ni < 8; ni++) {
            o[ni][0] *= corr0; o[ni][1] *= corr0;
            o[ni][2] *= corr1; o[ni][3] *= corr1;
        }

        // ---- O += P V (P frags are the packed exps directly) ----
        #pragma unroll
        for (int ks = 0; ks < 4; ks++) {
            uint32_t a0 = pe0[2*ks];
            uint32_t a1 = pe1[2*ks];
            uint32_t a2 = pe0[2*ks+1];
            uint32_t a3 = pe1[2*ks+1];
            #pragma unroll
            for (int np = 0; np < 4; np++) {
                uint32_t vf[4];
                int row = ks * 16 + (lane & 7) + ((lane >> 3) & 1) * 8;
                int col = np * 16 + ((lane >> 4) & 1) * 8;
                ldmat4t(vf, vb + (uint32_t)(row * ASTR + col) * 2);
                mma_f16(o[np*2],   a0, a1, a2, a3, vf[0], vf[1]);
                mma_f16(o[np*2+1], a0, a1, a2, a3, vf[2], vf[3]);
            }
        }
    }

    const float inv0 = 1.0f / l0;
    const float inv1 = 1.0f / l1;
    const int b = bh >> 4, h = bh & 15;
    __half* y0 = g_y + ((size_t)(b * T_ + row0)) * C_ + h * D_;
    __half* y1 = g_y + ((size_t)(b * T_ + row1)) * C_ + h * D_;
    #pragma unroll
    for (int ni = 0; ni < 8; ni++) {
        const int d = ni * 8 + lc * 2;
        *(__half2*)(y0 + d) = __floats2half2_rn(o[ni][0] * inv0, o[ni][1] * inv0);
        *(__half2*)(y1 + d) = __floats2half2_rn(o[ni][2] * inv1, o[ni][3] * inv1);
    }
}

// ---------------------------------------------------------------------------
extern "C" void kernel_launch(void* const* d_in, const int* in_sizes, int n_in,
                              void* d_out, int out_size)
{
    const float* q  = (const float*)d_in[0];
    const float* k  = (const float*)d_in[1];
    const float* v  = (const float*)d_in[2];
    // d_in[3] = causal mask (unused: causality handled analytically)
    const float* Wk = (const float*)d_in[4];
    const float* bk = (const float*)d_in[5];
    const float* Wc = (const float*)d_in[6];
    const float* bc = (const float*)d_in[7];
    float* out = (float*)d_out;

    cudaFuncSetAttribute(proj_h_kernel,
                         cudaFuncAttributeMaxDynamicSharedMemorySize, SMEM_GEMM_BYTES);
    cudaFuncSetAttribute(outproj_h_kernel,
                         cudaFuncAttributeMaxDynamicSharedMemorySize, SMEM_GEMM_BYTES);

    // 0) fp32 -> fp16 conversion of all GEMM operands
    cvt_kernel<<<dim3((M_*C_)/(256*4), 5), 256>>>(q, k, v, Wk, Wc);

    // 1) fused Q/K/V projection (fp16 mma.sync) -> [B,H,T,D] fp16 scratch
    proj_h_kernel<<<dim3(8, 16, 3), 256, SMEM_GEMM_BYTES>>>(bk);

    // 2) fp16 tensor-core causal flash attention -> g_y [B*T, C] fp16
    attn_h_kernel<<<dim3(16, 32), 128>>>();

    // 3) output projection (fp16 mma.sync) -> fp32 d_out
    outproj_h_kernel<<<dim3(8, 16, 1), 256, SMEM_GEMM_BYTES>>>(bc, out);
}

// round 8
// speedup vs baseline: 7.5027x; 1.0326x over previous
#include <cuda_runtime.h>
#include <cuda_fp16.h>
#include <cstdint>

#define B_ 2
#define T_ 1024
#define C_ 1024
#define H_ 16
#define D_ 64
#define M_ (B_*T_)   // 2048 rows

// fp16 scratch (static device globals: allocation-free per harness rules)
__device__ __half g_qh [(size_t)M_*C_];
__device__ __half g_kh [(size_t)M_*C_];
__device__ __half g_vh [(size_t)M_*C_];
__device__ __half g_Wkh[(size_t)C_*C_];
__device__ __half g_Wch[(size_t)C_*C_];
__device__ __half g_qp [(size_t)B_*H_*T_*D_]; // q pre-scaled by 0.125*log2(e)
__device__ __half g_kp [(size_t)B_*H_*T_*D_];
__device__ __half g_vp [(size_t)B_*H_*T_*D_];
__device__ __half g_y  [(size_t)M_*C_];

__device__ __forceinline__ uint32_t smem_u32(const void* p) {
    uint32_t a;
    asm("{ .reg .u64 t; cvta.to.shared.u64 t, %1; cvt.u32.u64 %0, t; }"
        : "=r"(a) : "l"(p));
    return a;
}

__device__ __forceinline__ uint32_t packh2(float a, float b) {
    __half2 h = __floats2half2_rn(a, b);
    return *(uint32_t*)&h;
}

__device__ __forceinline__ void mma_f16(
    float* c, uint32_t a0, uint32_t a1, uint32_t a2, uint32_t a3,
    uint32_t b0, uint32_t b1)
{
    asm volatile(
        "mma.sync.aligned.m16n8k16.row.col.f32.f16.f16.f32 "
        "{%0,%1,%2,%3}, {%4,%5,%6,%7}, {%8,%9}, {%0,%1,%2,%3};"
        : "+f"(c[0]), "+f"(c[1]), "+f"(c[2]), "+f"(c[3])
        : "r"(a0), "r"(a1), "r"(a2), "r"(a3), "r"(b0), "r"(b1));
}

__device__ __forceinline__ void ldmat4(uint32_t* r, uint32_t addr) {
    asm volatile("ldmatrix.sync.aligned.m8n8.x4.shared.b16 {%0,%1,%2,%3}, [%4];"
        : "=r"(r[0]), "=r"(r[1]), "=r"(r[2]), "=r"(r[3]) : "r"(addr));
}
__device__ __forceinline__ void ldmat4t(uint32_t* r, uint32_t addr) {
    asm volatile("ldmatrix.sync.aligned.m8n8.x4.trans.shared.b16 {%0,%1,%2,%3}, [%4];"
        : "=r"(r[0]), "=r"(r[1]), "=r"(r[2]), "=r"(r[3]) : "r"(addr));
}

// ---------------------------------------------------------------------------
// fp32 -> fp16 conversion of all GEMM inputs
// ---------------------------------------------------------------------------
__global__ void __launch_bounds__(256)
cvt_kernel(const float* __restrict__ q, const float* __restrict__ k,
           const float* __restrict__ v, const float* __restrict__ Wk,
           const float* __restrict__ Wc)
{
    const float* src; __half* dst; int n;
    switch (blockIdx.y) {
        case 0: src = q;  dst = g_qh;  n = M_*C_; break;
        case 1: src = k;  dst = g_kh;  n = M_*C_; break;
        case 2: src = v;  dst = g_vh;  n = M_*C_; break;
        case 3: src = Wk; dst = g_Wkh; n = C_*C_; break;
        default: src = Wc; dst = g_Wch; n = C_*C_; break;
    }
    int i = (blockIdx.x * 256 + threadIdx.x) * 4;
    if (i < n) {
        float4 f = *(const float4*)(src + i);
        *(__half2*)(dst + i)     = __floats2half2_rn(f.x, f.y);
        *(__half2*)(dst + i + 2) = __floats2half2_rn(f.z, f.w);
    }
}

// ---------------------------------------------------------------------------
// fp16 mma.sync GEMM: out = Xh[M,1024] @ Wh[1024,1024]^T + bias[1024]
// CTA 128x64, 128 threads (4 warps, warp tile 64x32), BK=32,
// 4-stage cp.async pipeline, swizzled SMEM, 4 CTAs/SM resident.
// ---------------------------------------------------------------------------
#define BKg 32
#define NCHg (C_/BKg)                  // 32
#define A_STAGE 8192                    // 128 rows * 64 B
#define B_STAGE 4096                    // 64 rows * 64 B
#define STAGE_BYTES (A_STAGE + B_STAGE) // 12288
#define SMEM_GEMM_BYTES (4 * STAGE_BYTES)   // 49152

// swizzled byte offset for (row, 16B-chunk c) in a 64B-row tile
__device__ __forceinline__ uint32_t swz64(int row, int c) {
    return (uint32_t)(row * 64 + ((c ^ ((row >> 1) & 3)) << 4));
}

__device__ __forceinline__ void gemm_h(
    const __half* __restrict__ X, const __half* __restrict__ W,
    const float* __restrict__ bias, void* __restrict__ out,
    int out_mode, float oscale)
{
    extern __shared__ __half smh[];
    const uint32_t sb = smem_u32(smh);

    const int tid  = threadIdx.x;
    const int wid  = tid >> 5;
    const int lane = tid & 31;
    const int warpM = (wid & 1) * 64;     // 2x2 warp grid
    const int warpN = (wid >> 1) * 32;
    const int m0 = blockIdx.y * 128;
    const int n0 = blockIdx.x * 64;
    const int lr = lane >> 2;
    const int lc = lane & 3;

    float acc[4][4][4];
    #pragma unroll
    for (int i = 0; i < 4; i++)
        #pragma unroll
        for (int j = 0; j < 4; j++)
            #pragma unroll
            for (int e = 0; e < 4; e++) acc[i][j][e] = 0.f;

    // loader: BK=32 halves = 64B = 4 x 16B chunks per row
    const int ldr = tid >> 2;             // 0..31
    const int ldc = tid & 3;              // chunk
    auto load_chunk = [&](int ch, int st) {
        const uint32_t base = sb + (uint32_t)st * STAGE_BYTES;
        #pragma unroll
        for (int i = 0; i < 4; i++) {     // A: 128 rows
            const int r = ldr + i * 32;
            const __half* gA = X + (size_t)(m0 + r) * C_ + ch * BKg + ldc * 8;
            asm volatile("cp.async.cg.shared.global [%0], [%1], 16;"
                         :: "r"(base + swz64(r, ldc)), "l"(gA));
        }
        #pragma unroll
        for (int i = 0; i < 2; i++) {     // B: 64 rows
            const int r = ldr + i * 32;
            const __half* gB = W + (size_t)(n0 + r) * C_ + ch * BKg + ldc * 8;
            asm volatile("cp.async.cg.shared.global [%0], [%1], 16;"
                         :: "r"(base + A_STAGE + swz64(r, ldc)), "l"(gB));
        }
        asm volatile("cp.async.commit_group;" ::: "memory");
    };

    load_chunk(0, 0);
    load_chunk(1, 1);

    for (int ch = 0; ch < NCHg; ch++) {
        const int st = ch & 3;
        if (ch + 2 < NCHg) {
            load_chunk(ch + 2, (ch + 2) & 3);
            asm volatile("cp.async.wait_group 2;" ::: "memory");
        } else if (ch + 1 < NCHg) {
            asm volatile("cp.async.wait_group 1;" ::: "memory");
        } else {
            asm volatile("cp.async.wait_group 0;" ::: "memory");
        }
        __syncthreads();

        const uint32_t aB = sb + (uint32_t)st * STAGE_BYTES;
        const uint32_t bB = aB + A_STAGE;

        #pragma unroll
        for (int kk = 0; kk < BKg; kk += 16) {
            const int kc = kk >> 3;
            uint32_t af[4][4], bf[2][4];
            #pragma unroll
            for (int mi = 0; mi < 4; mi++) {
                int row = warpM + mi * 16 + (lane & 15);
                int cc  = kc + (lane >> 4);
                ldmat4(af[mi], aB + swz64(row, cc));
            }
            #pragma unroll
            for (int np = 0; np < 2; np++) {
                int row = warpN + np * 16 + (lane & 7) + ((lane >> 4) & 1) * 8;
                int cc  = kc + ((lane >> 3) & 1);
                ldmat4(bf[np], bB + swz64(row, cc));
            }
            #pragma unroll
            for (int mi = 0; mi < 4; mi++)
                #pragma unroll
                for (int ni = 0; ni < 4; ni++)
                    mma_f16(acc[mi][ni],
                            af[mi][0], af[mi][1], af[mi][2], af[mi][3],
                            bf[ni >> 1][(ni & 1) * 2], bf[ni >> 1][(ni & 1) * 2 + 1]);
        }
    }

    #pragma unroll
    for (int mi = 0; mi < 4; mi++) {
        #pragma unroll
        for (int rr = 0; rr < 2; rr++) {
            const int m = m0 + warpM + mi * 16 + lr + rr * 8;
            #pragma unroll
            for (int ni = 0; ni < 4; ni++) {
                const int n = n0 + warpN + ni * 8 + lc * 2;
                float vx = (acc[mi][ni][rr*2+0] + bias[n])     * oscale;
                float vy = (acc[mi][ni][rr*2+1] + bias[n + 1]) * oscale;
                if (out_mode == 0) {
                    float2 vv = { vx, vy };
                    *(float2*)((float*)out + (size_t)m * C_ + n) = vv;
                } else {
                    const int b = m >> 10, t = m & (T_ - 1);
                    const int h = n >> 6,  d0 = n & (D_ - 1);
                    *(__half2*)((__half*)out +
                        (((size_t)(b * H_ + h)) * T_ + t) * D_ + d0) =
                        __floats2half2_rn(vx, vy);
                }
            }
        }
    }
}

__global__ void __launch_bounds__(128, 4)
proj_h_kernel(const float* __restrict__ bk)
{
    const __half* X = (blockIdx.z == 0) ? g_qh : (blockIdx.z == 1) ? g_kh : g_vh;
    __half* O = (blockIdx.z == 0) ? g_qp : (blockIdx.z == 1) ? g_kp : g_vp;
    // fold 1/sqrt(D) * log2(e) into Q so attention works in the log2 domain
    const float sc = (blockIdx.z == 0) ? 0.125f * 1.44269504f : 1.0f;
    gemm_h(X, g_Wkh, bk, O, 1, sc);
}

__global__ void __launch_bounds__(128, 4)
outproj_h_kernel(const float* __restrict__ bc, float* __restrict__ out)
{
    gemm_h(g_y, g_Wch, bc, out, 0, 1.0f);
}

// ---------------------------------------------------------------------------
// fp16 tensor-core causal flash attention (log2-domain softmax, ex2.f16x2).
// CTA: 64 q-rows of one (b,h); 4 warps x 16 rows; K/V double-buffered.
// ---------------------------------------------------------------------------
#define ASTR 72

__global__ void __launch_bounds__(128)
attn_h_kernel()
{
    __shared__ __half sQ[64 * ASTR];
    __shared__ __half sK[2][64 * ASTR];
    __shared__ __half sV[2][64 * ASTR];

    const int qt   = 15 - blockIdx.x;             // heavy tiles first
    const int bh   = blockIdx.y;
    const int tid  = threadIdx.x;
    const int w    = tid >> 5;
    const int lane = tid & 31;
    const int g    = lane >> 2;
    const int lc   = lane & 3;

    const __half* Qg = g_qp + (size_t)bh * T_ * D_;
    const __half* Kg = g_kp + (size_t)bh * T_ * D_;
    const __half* Vg = g_vp + (size_t)bh * T_ * D_;

    const int row0 = qt * 64 + w * 16 + g;
    const int row1 = row0 + 8;

    auto load_tile = [&](const __half* src, __half* dstTile, int rbase) {
        const uint32_t db = smem_u32(dstTile);
        #pragma unroll
        for (int i = 0; i < 4; i++) {
            int idx = tid + i * 128;
            int r   = idx >> 3;
            int c16 = idx & 7;
            const __half* gp = src + (size_t)(rbase + r) * D_ + c16 * 8;
            asm volatile("cp.async.cg.shared.global [%0], [%1], 16;"
                         :: "r"(db + (uint32_t)(r * ASTR + c16 * 8) * 2), "l"(gp));
        }
    };

    load_tile(Qg, sQ, qt * 64);
    load_tile(Kg, sK[0], 0);
    load_tile(Vg, sV[0], 0);
    asm volatile("cp.async.commit_group;" ::: "memory");

    float o[8][4];
    #pragma unroll
    for (int ni = 0; ni < 8; ni++)
        #pragma unroll
        for (int e = 0; e < 4; e++) o[ni][e] = 0.f;
    float m0 = -1e30f, m1 = -1e30f, l0 = 0.f, l1 = 0.f;

    uint32_t qf[4][4];
    const int nk = qt + 1;

    for (int kt = 0; kt < nk; kt++) {
        const int s = kt & 1;
        asm volatile("cp.async.wait_group 0;" ::: "memory");
        __syncthreads();
        if (kt + 1 < nk) {
            load_tile(Kg, sK[s ^ 1], (kt + 1) * 64);
            load_tile(Vg, sV[s ^ 1], (kt + 1) * 64);
            asm volatile("cp.async.commit_group;" ::: "memory");
        }
        if (kt == 0) {
            const uint32_t qb = smem_u32(sQ);
            #pragma unroll
            for (int ks = 0; ks < 4; ks++) {
                int row = w * 16 + (lane & 15);
                int col = ks * 16 + (lane >> 4) * 8;
                ldmat4(qf[ks], qb + (uint32_t)(row * ASTR + col) * 2);
            }
        }

        const uint32_t kb = smem_u32(sK[s]);
        const uint32_t vb = smem_u32(sV[s]);

        // ---- S = Q K^T (log2-domain) ----
        float p[8][4];
        #pragma unroll
        for (int ni = 0; ni < 8; ni++)
            #pragma unroll
            for (int e = 0; e < 4; e++) p[ni][e] = 0.f;

        #pragma unroll
        for (int ks = 0; ks < 4; ks++) {
            #pragma unroll
            for (int np = 0; np < 4; np++) {
                uint32_t kf[4];
                int row = np * 16 + (lane & 7) + ((lane >> 4) & 1) * 8;
                int col = ks * 16 + ((lane >> 3) & 1) * 8;
                ldmat4(kf, kb + (uint32_t)(row * ASTR + col) * 2);
                mma_f16(p[np*2],   qf[ks][0], qf[ks][1], qf[ks][2], qf[ks][3], kf[0], kf[1]);
                mma_f16(p[np*2+1], qf[ks][0], qf[ks][1], qf[ks][2], qf[ks][3], kf[2], kf[3]);
            }
        }

        if (kt == qt) {
            #pragma unroll
            for (int ni = 0; ni < 8; ni++) {
                const int c = kt * 64 + ni * 8 + lc * 2;
                if (c     > row0) p[ni][0] = -1e30f;
                if (c + 1 > row0) p[ni][1] = -1e30f;
                if (c     > row1) p[ni][2] = -1e30f;
                if (c + 1 > row1) p[ni][3] = -1e30f;
            }
        }

        // ---- online softmax (base-2) ----
        float rm0 = -1e30f, rm1 = -1e30f;
        #pragma unroll
        for (int ni = 0; ni < 8; ni++) {
            rm0 = fmaxf(rm0, fmaxf(p[ni][0], p[ni][1]));
            rm1 = fmaxf(rm1, fmaxf(p[ni][2], p[ni][3]));
        }
        rm0 = fmaxf(rm0, __shfl_xor_sync(0xffffffffu, rm0, 1));
        rm0 = fmaxf(rm0, __shfl_xor_sync(0xffffffffu, rm0, 2));
        rm1 = fmaxf(rm1, __shfl_xor_sync(0xffffffffu, rm1, 1));
        rm1 = fmaxf(rm1, __shfl_xor_sync(0xffffffffu, rm1, 2));

        const float mn0 = fmaxf(m0, rm0);
        const float mn1 = fmaxf(m1, rm1);
        const float corr0 = exp2f(m0 - mn0);
        const float corr1 = exp2f(m1 - mn1);
        m0 = mn0; m1 = mn1;

        uint32_t pe0[8], pe1[8];
        float rs0 = 0.f, rs1 = 0.f;
        #pragma unroll
        for (int ni = 0; ni < 8; ni++) {
            uint32_t ea = packh2(p[ni][0] - m0, p[ni][1] - m0);
            uint32_t eb = packh2(p[ni][2] - m1, p[ni][3] - m1);
            asm("ex2.approx.f16x2 %0, %0;" : "+r"(ea));
            asm("ex2.approx.f16x2 %0, %0;" : "+r"(eb));
            pe0[ni] = ea; pe1[ni] = eb;
            float2 fa = __half22float2(*(__half2*)&ea);
            float2 fb = __half22float2(*(__half2*)&eb);
            rs0 += fa.x + fa.y;
            rs1 += fb.x + fb.y;
        }
        rs0 += __shfl_xor_sync(0xffffffffu, rs0, 1);
        rs0 += __shfl_xor_sync(0xffffffffu, rs0, 2);
        rs1 += __shfl_xor_sync(0xffffffffu, rs1, 1);
        rs1 += __shfl_xor_sync(0xffffffffu, rs1, 2);
        l0 = l0 * corr0 + rs0;
        l1 = l1 * corr1 + rs1;

        #pragma unroll
        for (int ni = 0; ni < 8; ni++) {
            o[ni][0] *= corr0; o[ni][1] *= corr0;
            o[ni][2] *= corr1; o[ni][3] *= corr1;
        }

        // ---- O += P V ----
        #pragma unroll
        for (int ks = 0; ks < 4; ks++) {
            uint32_t a0 = pe0[2*ks];
            uint32_t a1 = pe1[2*ks];
            uint32_t a2 = pe0[2*ks+1];
            uint32_t a3 = pe1[2*ks+1];
            #pragma unroll
            for (int np = 0; np < 4; np++) {
                uint32_t vf[4];
                int row = ks * 16 + (lane & 7) + ((lane >> 3) & 1) * 8;
                int col = np * 16 + ((lane >> 4) & 1) * 8;
                ldmat4t(vf, vb + (uint32_t)(row * ASTR + col) * 2);
                mma_f16(o[np*2],   a0, a1, a2, a3, vf[0], vf[1]);
                mma_f16(o[np*2+1], a0, a1, a2, a3, vf[2], vf[3]);
            }
        }
    }

    const float inv0 = 1.0f / l0;
    const float inv1 = 1.0f / l1;
    const int b = bh >> 4, h = bh & 15;
    __half* y0 = g_y + ((size_t)(b * T_ + row0)) * C_ + h * D_;
    __half* y1 = g_y + ((size_t)(b * T_ + row1)) * C_ + h * D_;
    #pragma unroll
    for (int ni = 0; ni < 8; ni++) {
        const int d = ni * 8 + lc * 2;
        *(__half2*)(y0 + d) = __floats2half2_rn(o[ni][0] * inv0, o[ni][1] * inv0);
        *(__half2*)(y1 + d) = __floats2half2_rn(o[ni][2] * inv1, o[ni][3] * inv1);
    }
}

// ---------------------------------------------------------------------------
extern "C" void kernel_launch(void* const* d_in, const int* in_sizes, int n_in,
                              void* d_out, int out_size)
{
    const float* q  = (const float*)d_in[0];
    const float* k  = (const float*)d_in[1];
    const float* v  = (const float*)d_in[2];
    // d_in[3] = causal mask (unused: causality handled analytically)
    const float* Wk = (const float*)d_in[4];
    const float* bk = (const float*)d_in[5];
    const float* Wc = (const float*)d_in[6];
    const float* bc = (const float*)d_in[7];
    float* out = (float*)d_out;

    cudaFuncSetAttribute(proj_h_kernel,
                         cudaFuncAttributeMaxDynamicSharedMemorySize, SMEM_GEMM_BYTES);
    cudaFuncSetAttribute(outproj_h_kernel,
                         cudaFuncAttributeMaxDynamicSharedMemorySize, SMEM_GEMM_BYTES);

    // 0) fp32 -> fp16 conversion of all GEMM operands
    cvt_kernel<<<dim3((M_*C_)/(256*4), 5), 256>>>(q, k, v, Wk, Wc);

    // 1) fused Q/K/V projection (fp16 mma.sync) -> [B,H,T,D] fp16 scratch
    proj_h_kernel<<<dim3(C_/64, M_/128, 3), 128, SMEM_GEMM_BYTES>>>(bk);

    // 2) fp16 tensor-core causal flash attention -> g_y [B*T, C] fp16
    attn_h_kernel<<<dim3(16, 32), 128>>>();

    // 3) output projection (fp16 mma.sync) -> fp32 d_out
    outproj_h_kernel<<<dim3(C_/64, M_/128, 1), 128, SMEM_GEMM_BYTES>>>(bc, out);
}

// round 9
// speedup vs baseline: 7.5417x; 1.0052x over previous
#include <cuda_runtime.h>
#include <cuda_fp16.h>
#include <cstdint>

#define B_ 2
#define T_ 1024
#define C_ 1024
#define H_ 16
#define D_ 64
#define M_ (B_*T_)   // 2048 rows

// fp16 scratch (static device globals: allocation-free per harness rules)
__device__ __half g_qh [(size_t)M_*C_];
__device__ __half g_kh [(size_t)M_*C_];
__device__ __half g_vh [(size_t)M_*C_];
__device__ __half g_Wkh[(size_t)C_*C_];
__device__ __half g_Wch[(size_t)C_*C_];
__device__ __half g_qp [(size_t)B_*H_*T_*D_]; // q pre-scaled by 0.125*log2(e)
__device__ __half g_kp [(size_t)B_*H_*T_*D_];
__device__ __half g_vp [(size_t)B_*H_*T_*D_];
__device__ __half g_y  [(size_t)M_*C_];

__device__ __forceinline__ uint32_t smem_u32(const void* p) {
    uint32_t a;
    asm("{ .reg .u64 t; cvta.to.shared.u64 t, %1; cvt.u32.u64 %0, t; }"
        : "=r"(a) : "l"(p));
    return a;
}

__device__ __forceinline__ uint32_t packh2(float a, float b) {
    __half2 h = __floats2half2_rn(a, b);
    return *(uint32_t*)&h;
}

__device__ __forceinline__ void mma_f16(
    float* c, uint32_t a0, uint32_t a1, uint32_t a2, uint32_t a3,
    uint32_t b0, uint32_t b1)
{
    asm volatile(
        "mma.sync.aligned.m16n8k16.row.col.f32.f16.f16.f32 "
        "{%0,%1,%2,%3}, {%4,%5,%6,%7}, {%8,%9}, {%0,%1,%2,%3};"
        : "+f"(c[0]), "+f"(c[1]), "+f"(c[2]), "+f"(c[3])
        : "r"(a0), "r"(a1), "r"(a2), "r"(a3), "r"(b0), "r"(b1));
}

__device__ __forceinline__ void ldmat4(uint32_t* r, uint32_t addr) {
    asm volatile("ldmatrix.sync.aligned.m8n8.x4.shared.b16 {%0,%1,%2,%3}, [%4];"
        : "=r"(r[0]), "=r"(r[1]), "=r"(r[2]), "=r"(r[3]) : "r"(addr));
}
__device__ __forceinline__ void ldmat4t(uint32_t* r, uint32_t addr) {
    asm volatile("ldmatrix.sync.aligned.m8n8.x4.trans.shared.b16 {%0,%1,%2,%3}, [%4];"
        : "=r"(r[0]), "=r"(r[1]), "=r"(r[2]), "=r"(r[3]) : "r"(addr));
}

// ---------------------------------------------------------------------------
// fp32 -> fp16 conversion of all GEMM inputs
// ---------------------------------------------------------------------------
__global__ void __launch_bounds__(256)
cvt_kernel(const float* __restrict__ q, const float* __restrict__ k,
           const float* __restrict__ v, const float* __restrict__ Wk,
           const float* __restrict__ Wc)
{
    const float* src; __half* dst; int n;
    switch (blockIdx.y) {
        case 0: src = q;  dst = g_qh;  n = M_*C_; break;
        case 1: src = k;  dst = g_kh;  n = M_*C_; break;
        case 2: src = v;  dst = g_vh;  n = M_*C_; break;
        case 3: src = Wk; dst = g_Wkh; n = C_*C_; break;
        default: src = Wc; dst = g_Wch; n = C_*C_; break;
    }
    int i = (blockIdx.x * 256 + threadIdx.x) * 4;
    if (i < n) {
        float4 f = *(const float4*)(src + i);
        *(__half2*)(dst + i)     = __floats2half2_rn(f.x, f.y);
        *(__half2*)(dst + i + 2) = __floats2half2_rn(f.z, f.w);
    }
}

// ---------------------------------------------------------------------------
// fp16 mma.sync GEMM: out = Xh[M,1024] @ Wh[1024,1024]^T + bias[1024]
// CTA 128x64, 128 threads (4 warps, warp tile 64x32), BK=32,
// 4-stage cp.async pipeline, swizzled SMEM, 4 CTAs/SM resident.
// ---------------------------------------------------------------------------
#define BKg 32
#define NCHg (C_/BKg)                  // 32
#define A_STAGE 8192                    // 128 rows * 64 B
#define B_STAGE 4096                    // 64 rows * 64 B
#define STAGE_BYTES (A_STAGE + B_STAGE) // 12288
#define SMEM_GEMM_BYTES (4 * STAGE_BYTES)   // 49152

// swizzled byte offset for (row, 16B-chunk c) in a 64B-row tile
__device__ __forceinline__ uint32_t swz64(int row, int c) {
    return (uint32_t)(row * 64 + ((c ^ ((row >> 1) & 3)) << 4));
}

__device__ __forceinline__ void gemm_h(
    const __half* __restrict__ X, const __half* __restrict__ W,
    const float* __restrict__ bias, void* __restrict__ out,
    int out_mode, float oscale)
{
    extern __shared__ __half smh[];
    const uint32_t sb = smem_u32(smh);

    const int tid  = threadIdx.x;
    const int wid  = tid >> 5;
    const int lane = tid & 31;
    const int warpM = (wid & 1) * 64;     // 2x2 warp grid
    const int warpN = (wid >> 1) * 32;
    const int m0 = blockIdx.y * 128;
    const int n0 = blockIdx.x * 64;
    const int lr = lane >> 2;
    const int lc = lane & 3;

    float acc[4][4][4];
    #pragma unroll
    for (int i = 0; i < 4; i++)
        #pragma unroll
        for (int j = 0; j < 4; j++)
            #pragma unroll
            for (int e = 0; e < 4; e++) acc[i][j][e] = 0.f;

    // loader: BK=32 halves = 64B = 4 x 16B chunks per row
    const int ldr = tid >> 2;             // 0..31
    const int ldc = tid & 3;              // chunk
    auto load_chunk = [&](int ch, int st) {
        const uint32_t base = sb + (uint32_t)st * STAGE_BYTES;
        #pragma unroll
        for (int i = 0; i < 4; i++) {     // A: 128 rows
            const int r = ldr + i * 32;
            const __half* gA = X + (size_t)(m0 + r) * C_ + ch * BKg + ldc * 8;
            asm volatile("cp.async.cg.shared.global [%0], [%1], 16;"
                         :: "r"(base + swz64(r, ldc)), "l"(gA));
        }
        #pragma unroll
        for (int i = 0; i < 2; i++) {     // B: 64 rows
            const int r = ldr + i * 32;
            const __half* gB = W + (size_t)(n0 + r) * C_ + ch * BKg + ldc * 8;
            asm volatile("cp.async.cg.shared.global [%0], [%1], 16;"
                         :: "r"(base + A_STAGE + swz64(r, ldc)), "l"(gB));
        }
        asm volatile("cp.async.commit_group;" ::: "memory");
    };

    load_chunk(0, 0);
    load_chunk(1, 1);

    for (int ch = 0; ch < NCHg; ch++) {
        const int st = ch & 3;
        if (ch + 2 < NCHg) {
            load_chunk(ch + 2, (ch + 2) & 3);
            asm volatile("cp.async.wait_group 2;" ::: "memory");
        } else if (ch + 1 < NCHg) {
            asm volatile("cp.async.wait_group 1;" ::: "memory");
        } else {
            asm volatile("cp.async.wait_group 0;" ::: "memory");
        }
        __syncthreads();

        const uint32_t aB = sb + (uint32_t)st * STAGE_BYTES;
        const uint32_t bB = aB + A_STAGE;

        #pragma unroll
        for (int kk = 0; kk < BKg; kk += 16) {
            const int kc = kk >> 3;
            uint32_t af[4][4], bf[2][4];
            #pragma unroll
            for (int mi = 0; mi < 4; mi++) {
                int row = warpM + mi * 16 + (lane & 15);
                int cc  = kc + (lane >> 4);
                ldmat4(af[mi], aB + swz64(row, cc));
            }
            #pragma unroll
            for (int np = 0; np < 2; np++) {
                int row = warpN + np * 16 + (lane & 7) + ((lane >> 4) & 1) * 8;
                int cc  = kc + ((lane >> 3) & 1);
                ldmat4(bf[np], bB + swz64(row, cc));
            }
            #pragma unroll
            for (int mi = 0; mi < 4; mi++)
                #pragma unroll
                for (int ni = 0; ni < 4; ni++)
                    mma_f16(acc[mi][ni],
                            af[mi][0], af[mi][1], af[mi][2], af[mi][3],
                            bf[ni >> 1][(ni & 1) * 2], bf[ni >> 1][(ni & 1) * 2 + 1]);
        }
    }

    #pragma unroll
    for (int mi = 0; mi < 4; mi++) {
        #pragma unroll
        for (int rr = 0; rr < 2; rr++) {
            const int m = m0 + warpM + mi * 16 + lr + rr * 8;
            #pragma unroll
            for (int ni = 0; ni < 4; ni++) {
                const int n = n0 + warpN + ni * 8 + lc * 2;
                float vx = (acc[mi][ni][rr*2+0] + bias[n])     * oscale;
                float vy = (acc[mi][ni][rr*2+1] + bias[n + 1]) * oscale;
                if (out_mode == 0) {
                    float2 vv = { vx, vy };
                    *(float2*)((float*)out + (size_t)m * C_ + n) = vv;
                } else {
                    const int b = m >> 10, t = m & (T_ - 1);
                    const int h = n >> 6,  d0 = n & (D_ - 1);
                    *(__half2*)((__half*)out +
                        (((size_t)(b * H_ + h)) * T_ + t) * D_ + d0) =
                        __floats2half2_rn(vx, vy);
                }
            }
        }
    }
}

__global__ void __launch_bounds__(128, 4)
proj_h_kernel(const float* __restrict__ bk)
{
    const __half* X = (blockIdx.z == 0) ? g_qh : (blockIdx.z == 1) ? g_kh : g_vh;
    __half* O = (blockIdx.z == 0) ? g_qp : (blockIdx.z == 1) ? g_kp : g_vp;
    // fold 1/sqrt(D) * log2(e) into Q so attention works in the log2 domain
    const float sc = (blockIdx.z == 0) ? 0.125f * 1.44269504f : 1.0f;
    gemm_h(X, g_Wkh, bk, O, 1, sc);
}

__global__ void __launch_bounds__(128, 4)
outproj_h_kernel(const float* __restrict__ bc, float* __restrict__ out)
{
    gemm_h(g_y, g_Wch, bc, out, 0, 1.0f);
}

// ---------------------------------------------------------------------------
// fp16 tensor-core causal flash attention (log2-domain softmax, ex2.f16x2).
// CTA: 64 q-rows of one (b,h); 4 warps x 16 rows; K/V double-buffered.
// ---------------------------------------------------------------------------
#define ASTR 72

__global__ void __launch_bounds__(128)
attn_h_kernel()
{
    __shared__ __half sQ[64 * ASTR];
    __shared__ __half sK[2][64 * ASTR];
    __shared__ __half sV[2][64 * ASTR];

    const int qt   = 15 - blockIdx.x;             // heavy tiles first
    const int bh   = blockIdx.y;
    const int tid  = threadIdx.x;
    const int w    = tid >> 5;
    const int lane = tid & 31;
    const int g    = lane >> 2;
    const int lc   = lane & 3;

    const __half* Qg = g_qp + (size_t)bh * T_ * D_;
    const __half* Kg = g_kp + (size_t)bh * T_ * D_;
    const __half* Vg = g_vp + (size_t)bh * T_ * D_;

    const int row0 = qt * 64 + w * 16 + g;
    const int row1 = row0 + 8;

    auto load_tile = [&](const __half* src, __half* dstTile, int rbase) {
        const uint32_t db = smem_u32(dstTile);
        #pragma unroll
        for (int i = 0; i < 4; i++) {
            int idx = tid + i * 128;
            int r   = idx >> 3;
            int c16 = idx & 7;
            const __half* gp = src + (size_t)(rbase + r) * D_ + c16 * 8;
            asm volatile("cp.async.cg.shared.global [%0], [%1], 16;"
                         :: "r"(db + (uint32_t)(r * ASTR + c16 * 8) * 2), "l"(gp));
        }
    };

    load_tile(Qg, sQ, qt * 64);
    load_tile(Kg, sK[0], 0);
    load_tile(Vg, sV[0], 0);
    asm volatile("cp.async.commit_group;" ::: "memory");

    float o[8][4];
    #pragma unroll
    for (int ni = 0; ni < 8; ni++)
        #pragma unroll
        for (int e = 0; e < 4; e++) o[ni][e] = 0.f;
    float m0 = -1e30f, m1 = -1e30f, l0 = 0.f, l1 = 0.f;

    uint32_t qf[4][4];
    const int nk = qt + 1;

    for (int kt = 0; kt < nk; kt++) {
        const int s = kt & 1;
        asm volatile("cp.async.wait_group 0;" ::: "memory");
        __syncthreads();
        if (kt + 1 < nk) {
            load_tile(Kg, sK[s ^ 1], (kt + 1) * 64);
            load_tile(Vg, sV[s ^ 1], (kt + 1) * 64);
            asm volatile("cp.async.commit_group;" ::: "memory");
        }
        if (kt == 0) {
            const uint32_t qb = smem_u32(sQ);
            #pragma unroll
            for (int ks = 0; ks < 4; ks++) {
                int row = w * 16 + (lane & 15);
                int col = ks * 16 + (lane >> 4) * 8;
                ldmat4(qf[ks], qb + (uint32_t)(row * ASTR + col) * 2);
            }
        }

        const uint32_t kb = smem_u32(sK[s]);
        const uint32_t vb = smem_u32(sV[s]);

        // ---- S = Q K^T (log2-domain) ----
        float p[8][4];
        #pragma unroll
        for (int ni = 0; ni < 8; ni++)
            #pragma unroll
            for (int e = 0; e < 4; e++) p[ni][e] = 0.f;

        #pragma unroll
        for (int ks = 0; ks < 4; ks++) {
            #pragma unroll
            for (int np = 0; np < 4; np++) {
                uint32_t kf[4];
                int row = np * 16 + (lane & 7) + ((lane >> 4) & 1) * 8;
                int col = ks * 16 + ((lane >> 3) & 1) * 8;
                ldmat4(kf, kb + (uint32_t)(row * ASTR + col) * 2);
                mma_f16(p[np*2],   qf[ks][0], qf[ks][1], qf[ks][2], qf[ks][3], kf[0], kf[1]);
                mma_f16(p[np*2+1], qf[ks][0], qf[ks][1], qf[ks][2], qf[ks][3], kf[2], kf[3]);
            }
        }

        if (kt == qt) {
            #pragma unroll
            for (int ni = 0; ni < 8; ni++) {
                const int c = kt * 64 + ni * 8 + lc * 2;
                if (c     > row0) p[ni][0] = -1e30f;
                if (c + 1 > row0) p[ni][1] = -1e30f;
                if (c     > row1) p[ni][2] = -1e30f;
                if (c + 1 > row1) p[ni][3] = -1e30f;
            }
        }

        // ---- online softmax (base-2) ----
        float rm0 = -1e30f, rm1 = -1e30f;
        #pragma unroll
        for (int ni = 0; ni < 8; ni++) {
            rm0 = fmaxf(rm0, fmaxf(p[ni][0], p[ni][1]));
            rm1 = fmaxf(rm1, fmaxf(p[ni][2], p[ni][3]));
        }
        rm0 = fmaxf(rm0, __shfl_xor_sync(0xffffffffu, rm0, 1));
        rm0 = fmaxf(rm0, __shfl_xor_sync(0xffffffffu, rm0, 2));
        rm1 = fmaxf(rm1, __shfl_xor_sync(0xffffffffu, rm1, 1));
        rm1 = fmaxf(rm1, __shfl_xor_sync(0xffffffffu, rm1, 2));

        const float mn0 = fmaxf(m0, rm0);
        const float mn1 = fmaxf(m1, rm1);
        const float corr0 = exp2f(m0 - mn0);
        const float corr1 = exp2f(m1 - mn1);
        m0 = mn0; m1 = mn1;

        uint32_t pe0[8], pe1[8];
        float rs0 = 0.f, rs1 = 0.f;
        #pragma unroll
        for (int ni = 0; ni < 8; ni++) {
            uint32_t ea = packh2(p[ni][0] - m0, p[ni][1] - m0);
            uint32_t eb = packh2(p[ni][2] - m1, p[ni][3] - m1);
            asm("ex2.approx.f16x2 %0, %0;" : "+r"(ea));
            asm("ex2.approx.f16x2 %0, %0;" : "+r"(eb));
            pe0[ni] = ea; pe1[ni] = eb;
            float2 fa = __half22float2(*(__half2*)&ea);
            float2 fb = __half22float2(*(__half2*)&eb);
            rs0 += fa.x + fa.y;
            rs1 += fb.x + fb.y;
        }
        rs0 += __shfl_xor_sync(0xffffffffu, rs0, 1);
        rs0 += __shfl_xor_sync(0xffffffffu, rs0, 2);
        rs1 += __shfl_xor_sync(0xffffffffu, rs1, 1);
        rs1 += __shfl_xor_sync(0xffffffffu, rs1, 2);
        l0 = l0 * corr0 + rs0;
        l1 = l1 * corr1 + rs1;

        #pragma unroll
        for (int ni = 0; ni < 8; ni++) {
            o[ni][0] *= corr0; o[ni][1] *= corr0;
            o[ni][2] *= corr1; o[ni][3] *= corr1;
        }

        // ---- O += P V ----
        #pragma unroll
        for (int ks = 0; ks < 4; ks++) {
            uint32_t a0 = pe0[2*ks];
            uint32_t a1 = pe1[2*ks];
            uint32_t a2 = pe0[2*ks+1];
            uint32_t a3 = pe1[2*ks+1];
            #pragma unroll
            for (int np = 0; np < 4; np++) {
                uint32_t vf[4];
                int row = ks * 16 + (lane & 7) + ((lane >> 3) & 1) * 8;
                int col = np * 16 + ((lane >> 4) & 1) * 8;
                ldmat4t(vf, vb + (uint32_t)(row * ASTR + col) * 2);
                mma_f16(o[np*2],   a0, a1, a2, a3, vf[0], vf[1]);
                mma_f16(o[np*2+1], a0, a1, a2, a3, vf[2], vf[3]);
            }
        }
    }

    const float inv0 = 1.0f / l0;
    const float inv1 = 1.0f / l1;
    const int b = bh >> 4, h = bh & 15;
    __half* y0 = g_y + ((size_t)(b * T_ + row0)) * C_ + h * D_;
    __half* y1 = g_y + ((size_t)(b * T_ + row1)) * C_ + h * D_;
    #pragma unroll
    for (int ni = 0; ni < 8; ni++) {
        const int d = ni * 8 + lc * 2;
        *(__half2*)(y0 + d) = __floats2half2_rn(o[ni][0] * inv0, o[ni][1] * inv0);
        *(__half2*)(y1 + d) = __floats2half2_rn(o[ni][2] * inv1, o[ni][3] * inv1);
    }
}

// ---------------------------------------------------------------------------
extern "C" void kernel_launch(void* const* d_in, const int* in_sizes, int n_in,
                              void* d_out, int out_size)
{
    const float* q  = (const float*)d_in[0];
    const float* k  = (const float*)d_in[1];
    const float* v  = (const float*)d_in[2];
    // d_in[3] = causal mask (unused: causality handled analytically)
    const float* Wk = (const float*)d_in[4];
    const float* bk = (const float*)d_in[5];
    const float* Wc = (const float*)d_in[6];
    const float* bc = (const float*)d_in[7];
    float* out = (float*)d_out;

    cudaFuncSetAttribute(proj_h_kernel,
                         cudaFuncAttributeMaxDynamicSharedMemorySize, SMEM_GEMM_BYTES);
    cudaFuncSetAttribute(outproj_h_kernel,
                         cudaFuncAttributeMaxDynamicSharedMemorySize, SMEM_GEMM_BYTES);

    // 0) fp32 -> fp16 conversion of all GEMM operands
    cvt_kernel<<<dim3((M_*C_)/(256*4), 5), 256>>>(q, k, v, Wk, Wc);

    // 1) fused Q/K/V projection (fp16 mma.sync) -> [B,H,T,D] fp16 scratch
    proj_h_kernel<<<dim3(C_/64, M_/128, 3), 128, SMEM_GEMM_BYTES>>>(bk);

    // 2) fp16 tensor-core causal flash attention -> g_y [B*T, C] fp16
    attn_h_kernel<<<dim3(16, 32), 128>>>();

    // 3) output projection (fp16 mma.sync) -> fp32 d_out
    outproj_h_kernel<<<dim3(C_/64, M_/128, 1), 128, SMEM_GEMM_BYTES>>>(bc, out);
}